// round 9
// baseline (speedup 1.0000x reference)
#include <cuda_runtime.h>
#include <cuda_fp16.h>
#include <cstdint>
#include <math.h>

// ---------------------------------------------------------------------------
// Problem constants
// ---------------------------------------------------------------------------
#define B_     32
#define NQ_    4096
#define NK_    77
#define HEADS_ 8
#define DH_    40
#define INNER_ 320      // HEADS*DH
#define QDIM_  320
#define CDIM_  768

// Scratch (device globals: allocation-free per harness rules)
__device__ __half g_xh[(size_t)B_ * NQ_ * QDIM_];
__device__ __half g_ch[(size_t)B_ * NK_ * CDIM_];
__device__ __half g_qh[(size_t)B_ * NQ_ * INNER_];
__device__ __half g_kh[(size_t)B_ * NK_ * INNER_];
__device__ __half g_vh[(size_t)B_ * NK_ * INNER_];
__device__ __half g_wqh[INNER_ * QDIM_];
__device__ __half g_wkh[INNER_ * CDIM_];
__device__ __half g_wvh[INNER_ * CDIM_];
__device__ __half g_woh[QDIM_ * INNER_];

// ---------------------------------------------------------------------------
// Helpers
// ---------------------------------------------------------------------------
__device__ __forceinline__ uint32_t smem_u32(const void* p) {
    uint32_t a;
    asm("{ .reg .u64 t; cvta.to.shared.u64 t, %1; cvt.u32.u64 %0, t; }"
        : "=r"(a) : "l"(p));
    return a;
}
__device__ __forceinline__ void cp16(uint32_t dst, const void* src) {
    asm volatile("cp.async.cg.shared.global [%0], [%1], 16;" :: "r"(dst), "l"(src));
}
#define CP_COMMIT() asm volatile("cp.async.commit_group;" ::: "memory")
#define CP_WAIT(N)  asm volatile("cp.async.wait_group %0;" :: "n"(N) : "memory")

__device__ __forceinline__ void ldm_x4(uint32_t* r, uint32_t addr) {
    asm volatile("ldmatrix.sync.aligned.m8n8.x4.shared.b16 {%0,%1,%2,%3}, [%4];"
        : "=r"(r[0]), "=r"(r[1]), "=r"(r[2]), "=r"(r[3]) : "r"(addr));
}
__device__ __forceinline__ void ldm_x2(uint32_t* r, uint32_t addr) {
    asm volatile("ldmatrix.sync.aligned.m8n8.x2.shared.b16 {%0,%1}, [%2];"
        : "=r"(r[0]), "=r"(r[1]) : "r"(addr));
}
__device__ __forceinline__ void ldm_x4t(uint32_t* r, uint32_t addr) {
    asm volatile("ldmatrix.sync.aligned.m8n8.x4.trans.shared.b16 {%0,%1,%2,%3}, [%4];"
        : "=r"(r[0]), "=r"(r[1]), "=r"(r[2]), "=r"(r[3]) : "r"(addr));
}
__device__ __forceinline__ void ldm_x2t(uint32_t* r, uint32_t addr) {
    asm volatile("ldmatrix.sync.aligned.m8n8.x2.trans.shared.b16 {%0,%1}, [%2];"
        : "=r"(r[0]), "=r"(r[1]) : "r"(addr));
}
__device__ __forceinline__ void mma16816(float* c, const uint32_t* a,
                                         uint32_t b0, uint32_t b1) {
    asm volatile("mma.sync.aligned.m16n8k16.row.col.f32.f16.f16.f32 "
        "{%0,%1,%2,%3}, {%4,%5,%6,%7}, {%8,%9}, {%0,%1,%2,%3};"
        : "+f"(c[0]), "+f"(c[1]), "+f"(c[2]), "+f"(c[3])
        : "r"(a[0]), "r"(a[1]), "r"(a[2]), "r"(a[3]), "r"(b0), "r"(b1));
}
__device__ __forceinline__ void mma16808(float* c, const uint32_t* a, uint32_t b0) {
    asm volatile("mma.sync.aligned.m16n8k8.row.col.f32.f16.f16.f32 "
        "{%0,%1,%2,%3}, {%4,%5}, {%6}, {%0,%1,%2,%3};"
        : "+f"(c[0]), "+f"(c[1]), "+f"(c[2]), "+f"(c[3])
        : "r"(a[0]), "r"(a[1]), "r"(b0));
}
__device__ __forceinline__ unsigned f2h2(float a, float b) {
    __half2 h = __floats2half2_rn(a, b);
    return *reinterpret_cast<unsigned*>(&h);
}

// ---------------------------------------------------------------------------
// fp32 -> fp16 conversions
// ---------------------------------------------------------------------------
__global__ void f2h_kernel(const float* __restrict__ src,
                           __half* __restrict__ dst, int n4)
{
    int stride = gridDim.x * blockDim.x;
    for (int i = blockIdx.x * blockDim.x + threadIdx.x; i < n4; i += stride) {
        float4 f = ((const float4*)src)[i];
        uint2 u;
        u.x = f2h2(f.x, f.y);
        u.y = f2h2(f.z, f.w);
        ((uint2*)dst)[i] = u;
    }
}

// One launch converting 5 arrays (ctx + 4 weights), selected by blockIdx.y.
__global__ void f2h_multi(const float* s0, __half* d0, int n0,
                          const float* s1, __half* d1, int n1,
                          const float* s2, __half* d2, int n2,
                          const float* s3, __half* d3, int n3,
                          const float* s4, __half* d4, int n4c)
{
    const float* s; __half* d; int n;
    switch (blockIdx.y) {
        case 0: s = s0; d = d0; n = n0;  break;
        case 1: s = s1; d = d1; n = n1;  break;
        case 2: s = s2; d = d2; n = n2;  break;
        case 3: s = s3; d = d3; n = n3;  break;
        default: s = s4; d = d4; n = n4c; break;
    }
    int stride = gridDim.x * blockDim.x;
    for (int i = blockIdx.x * blockDim.x + threadIdx.x; i < n; i += stride) {
        float4 f = ((const float4*)s)[i];
        uint2 u;
        u.x = f2h2(f.x, f.y);
        u.y = f2h2(f.z, f.w);
        ((uint2*)d)[i] = u;
    }
}

// ---------------------------------------------------------------------------
// HMMA fp16 GEMM body:  C = (A@W^T + bias)*gamma
//   CTA 256m x 64n, 128 threads = 4 warps, warp tile 64m x 64n.
// ---------------------------------------------------------------------------
#define GTM 256
#define GTN 64
#define HROW 40
#define AS_STG (GTM * HROW)
#define BS_STG (GTN * HROW)
#define GSMEM ((3 * AS_STG + 3 * BS_STG) * 2)   // 76800 B

template<int KSTEPS, bool HALF_OUT, bool GUARD>
__device__ __forceinline__ void gemm_body(
    const __half* __restrict__ A, const __half* __restrict__ W,
    const float* __restrict__ gamma, const float* __restrict__ bias,
    void* __restrict__ Cv, int M, __half* dsm, int m0, int n0)
{
    constexpr int KD = KSTEPS * 32;
    __half (*As)[GTM][HROW] = (__half(*)[GTM][HROW])dsm;
    __half (*Bs)[GTN][HROW] = (__half(*)[GTN][HROW])(dsm + 3 * AS_STG);

    const int tid  = threadIdx.x;
    const int lane = tid & 31;
    const int wm   = (tid >> 5) * 64;

    const __half* paA[8];
    #pragma unroll
    for (int i = 0; i < 8; i++) {
        int c = tid + i * 128;
        int r = c >> 2, s = c & 3;
        int gr = m0 + r;
        if (GUARD) gr = min(gr, M - 1);
        paA[i] = A + (size_t)gr * KD + s * 8;
    }
    const __half* paB[2];
    #pragma unroll
    for (int i = 0; i < 2; i++) {
        int c = tid + i * 128;
        int r = c >> 2, s = c & 3;
        paB[i] = W + (size_t)(n0 + r) * KD + s * 8;
    }

    float acc[4][8][4];
    #pragma unroll
    for (int mt = 0; mt < 4; mt++)
        #pragma unroll
        for (int nt = 0; nt < 8; nt++)
            #pragma unroll
            for (int i = 0; i < 4; i++) acc[mt][nt][i] = 0.f;

    #pragma unroll
    for (int st = 0; st < 2; st++) {
        const int k0 = st * 32;
        #pragma unroll
        for (int i = 0; i < 8; i++) {
            int c = tid + i * 128;
            cp16(smem_u32(&As[st][c >> 2][(c & 3) * 8]), paA[i] + k0);
        }
        #pragma unroll
        for (int i = 0; i < 2; i++) {
            int c = tid + i * 128;
            cp16(smem_u32(&Bs[st][c >> 2][(c & 3) * 8]), paB[i] + k0);
        }
        CP_COMMIT();
    }

    int buf = 0, pbuf = 2;
    #pragma unroll 1
    for (int ks = 0; ks < KSTEPS; ks++) {
        if (ks + 1 < KSTEPS) { CP_WAIT(1); } else { CP_WAIT(0); }
        __syncthreads();
        if (ks + 2 < KSTEPS) {
            const int k0 = (ks + 2) * 32;
            #pragma unroll
            for (int i = 0; i < 8; i++) {
                int c = tid + i * 128;
                cp16(smem_u32(&As[pbuf][c >> 2][(c & 3) * 8]), paA[i] + k0);
            }
            #pragma unroll
            for (int i = 0; i < 2; i++) {
                int c = tid + i * 128;
                cp16(smem_u32(&Bs[pbuf][c >> 2][(c & 3) * 8]), paB[i] + k0);
            }
            CP_COMMIT();
        }

        #pragma unroll
        for (int kk = 0; kk < 32; kk += 16) {
            uint32_t af[4][4], bf[4][4];
            #pragma unroll
            for (int mt = 0; mt < 4; mt++)
                ldm_x4(af[mt], smem_u32(&As[buf][wm + mt * 16 + (lane & 15)]
                                             [kk + ((lane >> 4) & 1) * 8]));
            #pragma unroll
            for (int nh = 0; nh < 4; nh++)
                ldm_x4(bf[nh], smem_u32(&Bs[buf][nh * 16 + (lane & 7) + ((lane >> 4) << 3)]
                                             [kk + ((lane >> 3) & 1) * 8]));
            #pragma unroll
            for (int mt = 0; mt < 4; mt++)
                #pragma unroll
                for (int nt = 0; nt < 8; nt++)
                    mma16816(acc[mt][nt], af[mt],
                             bf[nt >> 1][(nt & 1) * 2], bf[nt >> 1][(nt & 1) * 2 + 1]);
        }

        buf  = (buf  == 2) ? 0 : buf  + 1;
        pbuf = (pbuf == 2) ? 0 : pbuf + 1;
    }

    #pragma unroll
    for (int nt = 0; nt < 8; nt++) {
        const int n = n0 + nt * 8 + (lane & 3) * 2;
        const float g0 = __ldg(&gamma[n]);
        const float g1 = __ldg(&gamma[n + 1]);
        const float b0 = bias ? __ldg(&bias[n])     : 0.f;
        const float b1 = bias ? __ldg(&bias[n + 1]) : 0.f;
        #pragma unroll
        for (int mt = 0; mt < 4; mt++) {
            const int r0 = m0 + wm + mt * 16 + (lane >> 2);
            float v00 = (acc[mt][nt][0] + b0) * g0;
            float v01 = (acc[mt][nt][1] + b1) * g1;
            float v10 = (acc[mt][nt][2] + b0) * g0;
            float v11 = (acc[mt][nt][3] + b1) * g1;
            if (HALF_OUT) {
                __half* C = (__half*)Cv;
                if (!GUARD || r0 < M)
                    *(uint32_t*)(C + (size_t)r0 * 320 + n) = f2h2(v00, v01);
                if (!GUARD || r0 + 8 < M)
                    *(uint32_t*)(C + (size_t)(r0 + 8) * 320 + n) = f2h2(v10, v11);
            } else {
                float* C = (float*)Cv;
                if (!GUARD || r0 < M) {
                    float2 p; p.x = v00; p.y = v01;
                    *(float2*)(C + (size_t)r0 * 320 + n) = p;
                }
                if (!GUARD || r0 + 8 < M) {
                    float2 p; p.x = v10; p.y = v11;
                    *(float2*)(C + (size_t)(r0 + 8) * 320 + n) = p;
                }
            }
        }
    }
}

template<int KSTEPS, bool HALF_OUT, bool GUARD>
__global__ void __launch_bounds__(128, 2)
gemm_hmma_t(const __half* __restrict__ A, const __half* __restrict__ W,
            const float* __restrict__ gamma, const float* __restrict__ bias,
            void* __restrict__ Cv, int M)
{
    extern __shared__ __half dsm[];
    gemm_body<KSTEPS, HALF_OUT, GUARD>(A, W, gamma, bias, Cv, M, dsm,
                                       blockIdx.y * GTM, blockIdx.x * GTN);
}

// K and V projections in one launch (blockIdx.z selects).
__global__ void __launch_bounds__(128, 2)
gemm_hmma_kv(const __half* __restrict__ A,
             const __half* __restrict__ Wk, const __half* __restrict__ Wv,
             const float* __restrict__ gk, const float* __restrict__ gv,
             __half* __restrict__ K, __half* __restrict__ V, int M)
{
    extern __shared__ __half dsm[];
    if (blockIdx.z == 0)
        gemm_body<24, true, true>(A, Wk, gk, nullptr, K, M, dsm,
                                  blockIdx.y * GTM, blockIdx.x * GTN);
    else
        gemm_body<24, true, true>(A, Wv, gv, nullptr, V, M, dsm,
                                  blockIdx.y * GTM, blockIdx.x * GTN);
}

// ---------------------------------------------------------------------------
// Fused attention + output projection.
//   CTA: (b, 128-query tile), 256 threads = 8 warps = 8 heads.
//   Smem: Qo[128][328] (q -> o in place), Ks/Vs[80][328].
//   After attention, Ks/Vs are overlaid by two full-n-chunk Wo buffers
//   (64 x 328 halves each) so the O-proj k-loop runs barrier-free.
// ---------------------------------------------------------------------------
#define QO_STRIDE 328
#define AO_QO   0
#define AO_KS   (128 * QO_STRIDE)                 // 41984 halves
#define AO_VS   (AO_KS + 80 * QO_STRIDE)          // 68224
#define AO_SMEM ((AO_VS + 80 * QO_STRIDE) * 2)    // 188928 B

__global__ void __launch_bounds__(256, 1)
attn_oproj(const __half* __restrict__ qh, const __half* __restrict__ kh,
           const __half* __restrict__ vh, const __half* __restrict__ woh,
           const float* __restrict__ gamma, const float* __restrict__ bias,
           float* __restrict__ out)
{
    extern __shared__ __half dsm[];
    __half* Qo = dsm + AO_QO;     // [128][328]
    __half* Ks = dsm + AO_KS;     // [80][328]  (later: Wo buffer A [64][328])
    __half* Vs = dsm + AO_VS;     // [80][328]  (later: Wo buffer B [64][328])

    const int b   = blockIdx.y;
    const int m0  = blockIdx.x * 128;
    const int tid = threadIdx.x, lane = tid & 31, wid = tid >> 5;

    const __half* qbase = qh + ((size_t)b * NQ_ + m0) * INNER_;
    const __half* kbase = kh + (size_t)b * NK_ * INNER_;
    const __half* vbase = vh + (size_t)b * NK_ * INNER_;

    // ---- stage q tile: 128 rows x 40 chunks ----
    #pragma unroll
    for (int i = 0; i < 20; i++) {
        int c = tid + i * 256;
        int r = c / 40, s = c % 40;
        cp16(smem_u32(&Qo[r * QO_STRIDE + s * 8]), qbase + (size_t)r * INNER_ + s * 8);
    }
    // ---- stage K, V: 77 rows x 40 chunks each ----
    for (int c = tid; c < 3080; c += 256) {
        int r = c / 40, s = c % 40;
        cp16(smem_u32(&Ks[r * QO_STRIDE + s * 8]), kbase + (size_t)r * INNER_ + s * 8);
        cp16(smem_u32(&Vs[r * QO_STRIDE + s * 8]), vbase + (size_t)r * INNER_ + s * 8);
    }
    CP_COMMIT();
    // zero key-pad rows 77-79 (disjoint from cp.async targets)
    if (tid < 120) {
        int r = 77 + tid / 40, s = tid % 40;
        const uint4 z4 = make_uint4(0, 0, 0, 0);
        *(uint4*)&Ks[r * QO_STRIDE + s * 8] = z4;
        *(uint4*)&Vs[r * QO_STRIDE + s * 8] = z4;
    }
    CP_WAIT(0);
    __syncthreads();

    // ---- attention: warp `wid` = head, all 128 queries, dh-exact ----
    {
        const int col0 = wid * DH_;
        const float scale = 0.15811388300841897f;   // 40^-0.5
        const int q2 = lane & 3;
        const bool ok0 = (72 + q2 * 2)     < 77;
        const bool ok1 = (72 + q2 * 2 + 1) < 77;

        #pragma unroll 1
        for (int mt = 0; mt < 8; mt++) {
            const int mrow = mt * 16;
            float w[10][4];
            #pragma unroll
            for (int nt = 0; nt < 10; nt++)
                #pragma unroll
                for (int i = 0; i < 4; i++) w[nt][i] = 0.f;

            // S = q K^T
            #pragma unroll
            for (int ksi = 0; ksi < 2; ksi++) {
                uint32_t af[4];
                ldm_x4(af, smem_u32(&Qo[(mrow + (lane & 15)) * QO_STRIDE
                                        + col0 + ksi * 16 + ((lane >> 4) & 1) * 8]));
                #pragma unroll
                for (int nh = 0; nh < 5; nh++) {
                    uint32_t bf[4];
                    ldm_x4(bf, smem_u32(&Ks[(nh * 16 + (lane & 7) + ((lane >> 4) << 3)) * QO_STRIDE
                                            + col0 + ksi * 16 + ((lane >> 3) & 1) * 8]));
                    mma16816(w[nh * 2],     af, bf[0], bf[1]);
                    mma16816(w[nh * 2 + 1], af, bf[2], bf[3]);
                }
            }
            {   // k8 tail (dh 32..39)
                uint32_t a8[2];
                ldm_x2(a8, smem_u32(&Qo[(mrow + (lane & 15)) * QO_STRIDE + col0 + 32]));
                #pragma unroll
                for (int nh = 0; nh < 5; nh++) {
                    uint32_t b8[2];
                    ldm_x2(b8, smem_u32(&Ks[(nh * 16 + (lane & 15)) * QO_STRIDE + col0 + 32]));
                    mma16808(w[nh * 2],     a8, b8[0]);
                    mma16808(w[nh * 2 + 1], a8, b8[1]);
                }
            }

            // softmax weights + row sums
            float s0 = 0.f, s1 = 0.f;
            #pragma unroll
            for (int nt = 0; nt < 10; nt++) {
                float e0 = __expf(w[nt][0] * scale);
                float e1 = __expf(w[nt][1] * scale);
                float e2 = __expf(w[nt][2] * scale);
                float e3 = __expf(w[nt][3] * scale);
                if (nt == 9) {
                    if (!ok0) { e0 = 0.f; e2 = 0.f; }
                    if (!ok1) { e1 = 0.f; e3 = 0.f; }
                }
                w[nt][0] = e0; w[nt][1] = e1;
                w[nt][2] = e2; w[nt][3] = e3;
                s0 += e0 + e1;
                s1 += e2 + e3;
            }
            s0 += __shfl_xor_sync(0xffffffffu, s0, 1);
            s0 += __shfl_xor_sync(0xffffffffu, s0, 2);
            s1 += __shfl_xor_sync(0xffffffffu, s1, 1);
            s1 += __shfl_xor_sync(0xffffffffu, s1, 2);
            const float inv0 = 1.f / s0;
            const float inv1 = 1.f / s1;

            // O = P V
            float oacc[5][4];
            #pragma unroll
            for (int nt = 0; nt < 5; nt++)
                #pragma unroll
                for (int i = 0; i < 4; i++) oacc[nt][i] = 0.f;

            #pragma unroll
            for (int kk = 0; kk < 5; kk++) {
                const int krow = kk * 16 + (lane & 7) + ((lane >> 3) & 1) * 8;
                uint32_t bA[4], bB[4], bC[2];
                ldm_x4t(bA, smem_u32(&Vs[krow * QO_STRIDE + col0 + ((lane >> 4) << 3)]));
                ldm_x4t(bB, smem_u32(&Vs[krow * QO_STRIDE + col0 + 16 + ((lane >> 4) << 3)]));
                ldm_x2t(bC, smem_u32(&Vs[krow * QO_STRIDE + col0 + 32]));
                uint32_t pa[4];
                pa[0] = f2h2(w[2 * kk][0],     w[2 * kk][1]);
                pa[1] = f2h2(w[2 * kk][2],     w[2 * kk][3]);
                pa[2] = f2h2(w[2 * kk + 1][0], w[2 * kk + 1][1]);
                pa[3] = f2h2(w[2 * kk + 1][2], w[2 * kk + 1][3]);
                mma16816(oacc[0], pa, bA[0], bA[1]);
                mma16816(oacc[1], pa, bA[2], bA[3]);
                mma16816(oacc[2], pa, bB[0], bB[1]);
                mma16816(oacc[3], pa, bB[2], bB[3]);
                mma16816(oacc[4], pa, bC[0], bC[1]);
            }

            // write o over q (warp-private column slice)
            const int r0 = mrow + (lane >> 2);
            #pragma unroll
            for (int nt = 0; nt < 5; nt++) {
                const int col = col0 + nt * 8 + q2 * 2;
                *(uint32_t*)&Qo[r0 * QO_STRIDE + col] =
                    f2h2(oacc[nt][0] * inv0, oacc[nt][1] * inv0);
                *(uint32_t*)&Qo[(r0 + 8) * QO_STRIDE + col] =
                    f2h2(oacc[nt][2] * inv1, oacc[nt][3] * inv1);
            }
        }
    }
    __syncthreads();   // all warps done with Ks/Vs and Qo writes

    // ---- output projection: out = (o @ Wo^T + bias) * gamma ----
    // Overlay: BsA = Ks region, BsB = Vs region; each holds one full
    // n-chunk of Wo: [64 rows][320 k] at stride 328.
    __half* BsA = Ks;
    __half* BsB = Vs;
    const int wm2 = (wid >> 1) * 32;
    const int wn2 = (wid & 1) * 32;

    // stage n-chunks 0 and 1 (2560 chunks each, 10 per thread)
    #pragma unroll
    for (int i = 0; i < 10; i++) {
        int c = tid + i * 256;
        int r = c / 40, s = c % 40;
        cp16(smem_u32(&BsA[r * QO_STRIDE + s * 8]), woh + (size_t)r * 320 + s * 8);
    }
    CP_COMMIT();
    #pragma unroll
    for (int i = 0; i < 10; i++) {
        int c = tid + i * 256;
        int r = c / 40, s = c % 40;
        cp16(smem_u32(&BsB[r * QO_STRIDE + s * 8]), woh + (size_t)(64 + r) * 320 + s * 8);
    }
    CP_COMMIT();

    #pragma unroll 1
    for (int nc = 0; nc < 5; nc++) {
        if (nc < 4) { CP_WAIT(1); } else { CP_WAIT(0); }
        __syncthreads();                         // chunk nc ready for all warps
        const __half* Bsn = (nc & 1) ? BsB : BsA;

        float acc[2][4][4];
        #pragma unroll
        for (int mt = 0; mt < 2; mt++)
            #pragma unroll
            for (int nt = 0; nt < 4; nt++)
                #pragma unroll
                for (int i = 0; i < 4; i++) acc[mt][nt][i] = 0.f;

        #pragma unroll 1
        for (int ks = 0; ks < 10; ks++) {        // barrier-free k loop
            #pragma unroll
            for (int kk = 0; kk < 32; kk += 16) {
                const int kg = ks * 32 + kk;
                uint32_t af[2][4], bf[2][4];
                #pragma unroll
                for (int mt = 0; mt < 2; mt++)
                    ldm_x4(af[mt], smem_u32(&Qo[(wm2 + mt * 16 + (lane & 15)) * QO_STRIDE
                                                + kg + ((lane >> 4) & 1) * 8]));
                #pragma unroll
                for (int nh = 0; nh < 2; nh++)
                    ldm_x4(bf[nh], smem_u32(&Bsn[(wn2 + nh * 16 + (lane & 7) + ((lane >> 4) << 3)) * QO_STRIDE
                                                 + kg + ((lane >> 3) & 1) * 8]));
                #pragma unroll
                for (int mt = 0; mt < 2; mt++)
                    #pragma unroll
                    for (int nt = 0; nt < 4; nt++)
                        mma16816(acc[mt][nt], af[mt],
                                 bf[nt >> 1][(nt & 1) * 2], bf[nt >> 1][(nt & 1) * 2 + 1]);
            }
        }

        __syncthreads();                         // buffer nc free for reuse
        if (nc + 2 < 5) {
            const int n0n = (nc + 2) * 64;
            __half* Bstg = (nc & 1) ? BsB : BsA;
            #pragma unroll
            for (int i = 0; i < 10; i++) {
                int c = tid + i * 256;
                int r = c / 40, s = c % 40;
                cp16(smem_u32(&Bstg[r * QO_STRIDE + s * 8]),
                     woh + (size_t)(n0n + r) * 320 + s * 8);
            }
            CP_COMMIT();
        }

        // epilogue for this n-chunk
        const int n0 = nc * 64;
        #pragma unroll
        for (int nt = 0; nt < 4; nt++) {
            const int n = n0 + wn2 + nt * 8 + (lane & 3) * 2;
            const float g0 = __ldg(&gamma[n]);
            const float g1 = __ldg(&gamma[n + 1]);
            const float b0v = __ldg(&bias[n]);
            const float b1v = __ldg(&bias[n + 1]);
            #pragma unroll
            for (int mt = 0; mt < 2; mt++) {
                const size_t row = (size_t)b * NQ_ + m0 + wm2 + mt * 16 + (lane >> 2);
                float2 p0, p1;
                p0.x = (acc[mt][nt][0] + b0v) * g0;
                p0.y = (acc[mt][nt][1] + b1v) * g1;
                p1.x = (acc[mt][nt][2] + b0v) * g0;
                p1.y = (acc[mt][nt][3] + b1v) * g1;
                *(float2*)(out + row * 320 + n)       = p0;
                *(float2*)(out + (row + 8) * 320 + n) = p1;
            }
        }
    }
}

// ---------------------------------------------------------------------------
// Launch
// ---------------------------------------------------------------------------
extern "C" void kernel_launch(void* const* d_in, const int* in_sizes, int n_in,
                              void* d_out, int out_size)
{
    (void)in_sizes; (void)n_in; (void)out_size;
    const float* x   = (const float*)d_in[0];
    const float* ctx = (const float*)d_in[1];
    const float* Wq  = (const float*)d_in[2];
    const float* Wk  = (const float*)d_in[3];
    const float* Wv  = (const float*)d_in[4];
    const float* Wo  = (const float*)d_in[5];
    const float* bo  = (const float*)d_in[6];
    const float* gq  = (const float*)d_in[7];
    const float* gk  = (const float*)d_in[8];
    const float* gv  = (const float*)d_in[9];
    const float* go  = (const float*)d_in[10];
    float* out = (float*)d_out;

    __half *xh, *ch, *qh, *kh, *vh, *wqh, *wkh, *wvh, *woh;
    cudaGetSymbolAddress((void**)&xh,  g_xh);
    cudaGetSymbolAddress((void**)&ch,  g_ch);
    cudaGetSymbolAddress((void**)&qh,  g_qh);
    cudaGetSymbolAddress((void**)&kh,  g_kh);
    cudaGetSymbolAddress((void**)&vh,  g_vh);
    cudaGetSymbolAddress((void**)&wqh, g_wqh);
    cudaGetSymbolAddress((void**)&wkh, g_wkh);
    cudaGetSymbolAddress((void**)&wvh, g_wvh);
    cudaGetSymbolAddress((void**)&woh, g_woh);

    cudaFuncSetAttribute(gemm_hmma_t<10, true, false>, cudaFuncAttributeMaxDynamicSharedMemorySize, GSMEM);
    cudaFuncSetAttribute(gemm_hmma_kv, cudaFuncAttributeMaxDynamicSharedMemorySize, GSMEM);
    cudaFuncSetAttribute(attn_oproj, cudaFuncAttributeMaxDynamicSharedMemorySize, AO_SMEM);

    const int Mq  = B_ * NQ_;   // 131072
    const int Mkv = B_ * NK_;   // 2464

    dim3 thr(128);
    dim3 grid_q (320 / GTN, Mq / GTM);                   // (5, 512)
    dim3 grid_kv(320 / GTN, (Mkv + GTM - 1) / GTM, 2);   // (5, 10, 2)
    dim3 grid_ao(NQ_ / 128, B_);                         // (32, 32)

    // conversions: big x separately; ctx + 4 weights in one launch
    f2h_kernel<<<4096, 256>>>(x, xh, Mq * QDIM_ / 4);
    f2h_multi<<<dim3(512, 5), 256>>>(
        ctx, ch,  Mkv * CDIM_ / 4,
        Wq,  wqh, INNER_ * QDIM_ / 4,
        Wk,  wkh, INNER_ * CDIM_ / 4,
        Wv,  wvh, INNER_ * CDIM_ / 4,
        Wo,  woh, QDIM_ * INNER_ / 4);

    // K + V projections in one launch (K=768, fp16 out, guarded)
    gemm_hmma_kv<<<grid_kv, thr, GSMEM>>>(ch, wkh, wvh, gk, gv, kh, vh, Mkv);

    // Q projection (K=320, fp16 out)
    gemm_hmma_t<10, true, false><<<grid_q, thr, GSMEM>>>(xh, wqh, gq, nullptr, qh, Mq);

    // fused attention + output projection
    attn_oproj<<<grid_ao, 256, AO_SMEM>>>(qh, kh, vh, woh, go, bo, out);
}

// round 12
// speedup vs baseline: 1.3096x; 1.3096x over previous
#include <cuda_runtime.h>
#include <cuda_fp16.h>
#include <cstdint>
#include <math.h>

// ---------------------------------------------------------------------------
// Problem constants
// ---------------------------------------------------------------------------
#define B_     32
#define NQ_    4096
#define NK_    77
#define HEADS_ 8
#define DH_    40
#define INNER_ 320      // HEADS*DH
#define QDIM_  320
#define CDIM_  768

// Scratch (device globals: allocation-free per harness rules)
__device__ __half g_xh[(size_t)B_ * NQ_ * QDIM_];
__device__ __half g_ch[(size_t)B_ * NK_ * CDIM_];
__device__ __half g_qh[(size_t)B_ * NQ_ * INNER_];
__device__ __half g_kh[(size_t)B_ * NK_ * INNER_];
__device__ __half g_vh[(size_t)B_ * NK_ * INNER_];
__device__ __half g_wqh[INNER_ * QDIM_];
__device__ __half g_wkh[INNER_ * CDIM_];
__device__ __half g_wvh[INNER_ * CDIM_];
__device__ __half g_woh[QDIM_ * INNER_];

// ---------------------------------------------------------------------------
// Helpers
// ---------------------------------------------------------------------------
__device__ __forceinline__ uint32_t smem_u32(const void* p) {
    uint32_t a;
    asm("{ .reg .u64 t; cvta.to.shared.u64 t, %1; cvt.u32.u64 %0, t; }"
        : "=r"(a) : "l"(p));
    return a;
}
__device__ __forceinline__ void cp16(uint32_t dst, const void* src) {
    asm volatile("cp.async.cg.shared.global [%0], [%1], 16;" :: "r"(dst), "l"(src));
}
#define CP_COMMIT() asm volatile("cp.async.commit_group;" ::: "memory")
#define CP_WAIT(N)  asm volatile("cp.async.wait_group %0;" :: "n"(N) : "memory")

__device__ __forceinline__ void ldm_x4(uint32_t* r, uint32_t addr) {
    asm volatile("ldmatrix.sync.aligned.m8n8.x4.shared.b16 {%0,%1,%2,%3}, [%4];"
        : "=r"(r[0]), "=r"(r[1]), "=r"(r[2]), "=r"(r[3]) : "r"(addr));
}
__device__ __forceinline__ void ldm_x2(uint32_t* r, uint32_t addr) {
    asm volatile("ldmatrix.sync.aligned.m8n8.x2.shared.b16 {%0,%1}, [%2];"
        : "=r"(r[0]), "=r"(r[1]) : "r"(addr));
}
__device__ __forceinline__ void ldm_x4t(uint32_t* r, uint32_t addr) {
    asm volatile("ldmatrix.sync.aligned.m8n8.x4.trans.shared.b16 {%0,%1,%2,%3}, [%4];"
        : "=r"(r[0]), "=r"(r[1]), "=r"(r[2]), "=r"(r[3]) : "r"(addr));
}
__device__ __forceinline__ void ldm_x2t(uint32_t* r, uint32_t addr) {
    asm volatile("ldmatrix.sync.aligned.m8n8.x2.trans.shared.b16 {%0,%1}, [%2];"
        : "=r"(r[0]), "=r"(r[1]) : "r"(addr));
}
__device__ __forceinline__ void mma16816(float* c, const uint32_t* a,
                                         uint32_t b0, uint32_t b1) {
    asm volatile("mma.sync.aligned.m16n8k16.row.col.f32.f16.f16.f32 "
        "{%0,%1,%2,%3}, {%4,%5,%6,%7}, {%8,%9}, {%0,%1,%2,%3};"
        : "+f"(c[0]), "+f"(c[1]), "+f"(c[2]), "+f"(c[3])
        : "r"(a[0]), "r"(a[1]), "r"(a[2]), "r"(a[3]), "r"(b0), "r"(b1));
}
__device__ __forceinline__ void mma16808(float* c, const uint32_t* a, uint32_t b0) {
    asm volatile("mma.sync.aligned.m16n8k8.row.col.f32.f16.f16.f32 "
        "{%0,%1,%2,%3}, {%4,%5}, {%6}, {%0,%1,%2,%3};"
        : "+f"(c[0]), "+f"(c[1]), "+f"(c[2]), "+f"(c[3])
        : "r"(a[0]), "r"(a[1]), "r"(b0));
}
__device__ __forceinline__ unsigned f2h2(float a, float b) {
    __half2 h = __floats2half2_rn(a, b);
    return *reinterpret_cast<unsigned*>(&h);
}

// ---------------------------------------------------------------------------
// fp32 -> fp16 conversion
// ---------------------------------------------------------------------------
__global__ void f2h_kernel(const float* __restrict__ src,
                           __half* __restrict__ dst, int n4)
{
    int stride = gridDim.x * blockDim.x;
    for (int i = blockIdx.x * blockDim.x + threadIdx.x; i < n4; i += stride) {
        float4 f = ((const float4*)src)[i];
        uint2 u;
        u.x = f2h2(f.x, f.y);
        u.y = f2h2(f.z, f.w);
        ((uint2*)dst)[i] = u;
    }
}

// ---------------------------------------------------------------------------
// HMMA fp16 GEMM:  C = (A@W^T + bias)*gamma
//   CTA 192m x 64n, 128 threads = 4 warps, warp tile 48m x 64n.
//   3-stage cp.async pipeline, 3 CTAs/SM (regs ~140, smem 61.4KB).
// ---------------------------------------------------------------------------
#define GTM 192
#define GTN 64
#define HROW 40
#define AS_STG (GTM * HROW)          // 7680 halves per A stage
#define BS_STG (GTN * HROW)          // 2560 halves per B stage
#define GSMEM ((3 * AS_STG + 3 * BS_STG) * 2)   // 61440 B

template<int KSTEPS, bool HALF_OUT>
__global__ void __launch_bounds__(128, 3)
gemm_hmma_t(const __half* __restrict__ A,
            const __half* __restrict__ W,
            const float* __restrict__ gamma,
            const float* __restrict__ bias,
            void* __restrict__ Cv,
            int M)
{
    constexpr int KD = KSTEPS * 32;
    extern __shared__ __half dsm[];
    __half (*As)[GTM][HROW] = (__half(*)[GTM][HROW])dsm;
    __half (*Bs)[GTN][HROW] = (__half(*)[GTN][HROW])(dsm + 3 * AS_STG);

    const int tid  = threadIdx.x;
    const int lane = tid & 31;
    const int wm   = (tid >> 5) * 48;        // warp m offset 0,48,96,144
    const int n0   = blockIdx.x * GTN;
    const int m0   = blockIdx.y * GTM;

    // staging rows (A: 6 chunks/thread -> rows (tid>>2)+32i; B: 2 chunks)
    const int srow = tid >> 2;
    const int scol = (tid & 3) * 8;
    int rowA[6];
    #pragma unroll
    for (int i = 0; i < 6; i++) rowA[i] = min(m0 + srow + 32 * i, M - 1);

    float acc[3][8][4];
    #pragma unroll
    for (int mt = 0; mt < 3; mt++)
        #pragma unroll
        for (int nt = 0; nt < 8; nt++)
            #pragma unroll
            for (int i = 0; i < 4; i++) acc[mt][nt][i] = 0.f;

    // prologue: stages 0, 1
    #pragma unroll
    for (int st = 0; st < 2; st++) {
        const int k0 = st * 32;
        #pragma unroll
        for (int i = 0; i < 6; i++)
            cp16(smem_u32(&As[st][srow + 32 * i][scol]),
                 A + (size_t)rowA[i] * KD + k0 + scol);
        #pragma unroll
        for (int i = 0; i < 2; i++)
            cp16(smem_u32(&Bs[st][srow + 32 * i][scol]),
                 W + (size_t)(n0 + srow + 32 * i) * KD + k0 + scol);
        CP_COMMIT();
    }

    int buf = 0, pbuf = 2;
    #pragma unroll 1
    for (int ks = 0; ks < KSTEPS; ks++) {
        if (ks + 1 < KSTEPS) { CP_WAIT(1); } else { CP_WAIT(0); }
        __syncthreads();
        if (ks + 2 < KSTEPS) {
            const int k0 = (ks + 2) * 32;
            #pragma unroll
            for (int i = 0; i < 6; i++)
                cp16(smem_u32(&As[pbuf][srow + 32 * i][scol]),
                     A + (size_t)rowA[i] * KD + k0 + scol);
            #pragma unroll
            for (int i = 0; i < 2; i++)
                cp16(smem_u32(&Bs[pbuf][srow + 32 * i][scol]),
                     W + (size_t)(n0 + srow + 32 * i) * KD + k0 + scol);
            CP_COMMIT();
        }

        #pragma unroll
        for (int kk = 0; kk < 32; kk += 16) {
            uint32_t af[3][4];
            #pragma unroll
            for (int mt = 0; mt < 3; mt++)
                ldm_x4(af[mt], smem_u32(&As[buf][wm + mt * 16 + (lane & 15)]
                                             [kk + ((lane >> 4) & 1) * 8]));
            #pragma unroll
            for (int nh = 0; nh < 4; nh++) {
                uint32_t bf[4];
                ldm_x4(bf, smem_u32(&Bs[buf][nh * 16 + (lane & 7) + ((lane >> 4) << 3)]
                                         [kk + ((lane >> 3) & 1) * 8]));
                #pragma unroll
                for (int mt = 0; mt < 3; mt++) {
                    mma16816(acc[mt][nh * 2],     af[mt], bf[0], bf[1]);
                    mma16816(acc[mt][nh * 2 + 1], af[mt], bf[2], bf[3]);
                }
            }
        }

        buf  = (buf  == 2) ? 0 : buf  + 1;
        pbuf = (pbuf == 2) ? 0 : pbuf + 1;
    }

    // epilogue: (acc + bias) * gamma
    #pragma unroll
    for (int nt = 0; nt < 8; nt++) {
        const int n = n0 + nt * 8 + (lane & 3) * 2;
        const float g0 = __ldg(&gamma[n]);
        const float g1 = __ldg(&gamma[n + 1]);
        const float b0 = bias ? __ldg(&bias[n])     : 0.f;
        const float b1 = bias ? __ldg(&bias[n + 1]) : 0.f;
        #pragma unroll
        for (int mt = 0; mt < 3; mt++) {
            const int r0 = m0 + wm + mt * 16 + (lane >> 2);
            float v00 = (acc[mt][nt][0] + b0) * g0;
            float v01 = (acc[mt][nt][1] + b1) * g1;
            float v10 = (acc[mt][nt][2] + b0) * g0;
            float v11 = (acc[mt][nt][3] + b1) * g1;
            if (HALF_OUT) {
                __half* C = (__half*)Cv;
                if (r0 < M)
                    *(uint32_t*)(C + (size_t)r0 * 320 + n) = f2h2(v00, v01);
                if (r0 + 8 < M)
                    *(uint32_t*)(C + (size_t)(r0 + 8) * 320 + n) = f2h2(v10, v11);
            } else {
                float* C = (float*)Cv;
                if (r0 < M) {
                    float2 p; p.x = v00; p.y = v01;
                    *(float2*)(C + (size_t)r0 * 320 + n) = p;
                }
                if (r0 + 8 < M) {
                    float2 p; p.x = v10; p.y = v11;
                    *(float2*)(C + (size_t)(r0 + 8) * 320 + n) = p;
                }
            }
        }
    }
}

// ---------------------------------------------------------------------------
// Fused attention + output projection (R8-proven version).
//   CTA: (b, 128-query tile), 256 threads = 8 warps = 8 heads.
// ---------------------------------------------------------------------------
#define QO_STRIDE 328
#define AO_QO   0
#define AO_KS   (128 * QO_STRIDE)                 // 41984
#define AO_VS   (AO_KS + 80 * QO_STRIDE)          // 68224
#define AO_BS   (AO_VS + 80 * QO_STRIDE)          // 94464
#define AO_SMEM ((AO_BS + 3 * 64 * 40) * 2)       // 204288 B

__global__ void __launch_bounds__(256, 1)
attn_oproj(const __half* __restrict__ qh, const __half* __restrict__ kh,
           const __half* __restrict__ vh, const __half* __restrict__ woh,
           const float* __restrict__ gamma, const float* __restrict__ bias,
           float* __restrict__ out)
{
    extern __shared__ __half dsm[];
    __half* Qo = dsm + AO_QO;     // [128][328]
    __half* Ks = dsm + AO_KS;     // [80][328]
    __half* Vs = dsm + AO_VS;     // [80][328]
    __half* Bs = dsm + AO_BS;     // [3][64][40]

    const int b   = blockIdx.y;
    const int m0  = blockIdx.x * 128;
    const int tid = threadIdx.x, lane = tid & 31, wid = tid >> 5;

    const __half* qbase = qh + ((size_t)b * NQ_ + m0) * INNER_;
    const __half* kbase = kh + (size_t)b * NK_ * INNER_;
    const __half* vbase = vh + (size_t)b * NK_ * INNER_;

    // ---- stage q tile: 128 rows x 40 chunks ----
    #pragma unroll
    for (int i = 0; i < 20; i++) {
        int c = tid + i * 256;
        int r = c / 40, s = c % 40;
        cp16(smem_u32(&Qo[r * QO_STRIDE + s * 8]), qbase + (size_t)r * INNER_ + s * 8);
    }
    // ---- stage K, V: 77 rows x 40 chunks each ----
    for (int c = tid; c < 3080; c += 256) {
        int r = c / 40, s = c % 40;
        cp16(smem_u32(&Ks[r * QO_STRIDE + s * 8]), kbase + (size_t)r * INNER_ + s * 8);
        cp16(smem_u32(&Vs[r * QO_STRIDE + s * 8]), vbase + (size_t)r * INNER_ + s * 8);
    }
    CP_COMMIT();
    // zero key-pad rows 77-79 (disjoint from cp.async targets)
    if (tid < 120) {
        int r = 77 + tid / 40, s = tid % 40;
        const uint4 z4 = make_uint4(0, 0, 0, 0);
        *(uint4*)&Ks[r * QO_STRIDE + s * 8] = z4;
        *(uint4*)&Vs[r * QO_STRIDE + s * 8] = z4;
    }
    CP_WAIT(0);
    __syncthreads();

    // ---- attention: warp `wid` = head, all 128 queries, dh-exact ----
    {
        const int col0 = wid * DH_;
        const float scale = 0.15811388300841897f;   // 40^-0.5
        const int q2 = lane & 3;
        const bool ok0 = (72 + q2 * 2)     < 77;
        const bool ok1 = (72 + q2 * 2 + 1) < 77;

        #pragma unroll 1
        for (int mt = 0; mt < 8; mt++) {
            const int mrow = mt * 16;
            float w[10][4];
            #pragma unroll
            for (int nt = 0; nt < 10; nt++)
                #pragma unroll
                for (int i = 0; i < 4; i++) w[nt][i] = 0.f;

            // S = q K^T
            #pragma unroll
            for (int ksi = 0; ksi < 2; ksi++) {
                uint32_t af[4];
                ldm_x4(af, smem_u32(&Qo[(mrow + (lane & 15)) * QO_STRIDE
                                        + col0 + ksi * 16 + ((lane >> 4) & 1) * 8]));
                #pragma unroll
                for (int nh = 0; nh < 5; nh++) {
                    uint32_t bf[4];
                    ldm_x4(bf, smem_u32(&Ks[(nh * 16 + (lane & 7) + ((lane >> 4) << 3)) * QO_STRIDE
                                            + col0 + ksi * 16 + ((lane >> 3) & 1) * 8]));
                    mma16816(w[nh * 2],     af, bf[0], bf[1]);
                    mma16816(w[nh * 2 + 1], af, bf[2], bf[3]);
                }
            }
            {   // k8 tail (dh 32..39)
                uint32_t a8[2];
                ldm_x2(a8, smem_u32(&Qo[(mrow + (lane & 15)) * QO_STRIDE + col0 + 32]));
                #pragma unroll
                for (int nh = 0; nh < 5; nh++) {
                    uint32_t b8[2];
                    ldm_x2(b8, smem_u32(&Ks[(nh * 16 + (lane & 15)) * QO_STRIDE + col0 + 32]));
                    mma16808(w[nh * 2],     a8, b8[0]);
                    mma16808(w[nh * 2 + 1], a8, b8[1]);
                }
            }

            // softmax weights + row sums
            float s0 = 0.f, s1 = 0.f;
            #pragma unroll
            for (int nt = 0; nt < 10; nt++) {
                float e0 = __expf(w[nt][0] * scale);
                float e1 = __expf(w[nt][1] * scale);
                float e2 = __expf(w[nt][2] * scale);
                float e3 = __expf(w[nt][3] * scale);
                if (nt == 9) {
                    if (!ok0) { e0 = 0.f; e2 = 0.f; }
                    if (!ok1) { e1 = 0.f; e3 = 0.f; }
                }
                w[nt][0] = e0; w[nt][1] = e1;
                w[nt][2] = e2; w[nt][3] = e3;
                s0 += e0 + e1;
                s1 += e2 + e3;
            }
            s0 += __shfl_xor_sync(0xffffffffu, s0, 1);
            s0 += __shfl_xor_sync(0xffffffffu, s0, 2);
            s1 += __shfl_xor_sync(0xffffffffu, s1, 1);
            s1 += __shfl_xor_sync(0xffffffffu, s1, 2);
            const float inv0 = 1.f / s0;
            const float inv1 = 1.f / s1;

            // O = P V
            float oacc[5][4];
            #pragma unroll
            for (int nt = 0; nt < 5; nt++)
                #pragma unroll
                for (int i = 0; i < 4; i++) oacc[nt][i] = 0.f;

            #pragma unroll
            for (int kk = 0; kk < 5; kk++) {
                const int krow = kk * 16 + (lane & 7) + ((lane >> 3) & 1) * 8;
                uint32_t bA[4], bB[4], bC[2];
                ldm_x4t(bA, smem_u32(&Vs[krow * QO_STRIDE + col0 + ((lane >> 4) << 3)]));
                ldm_x4t(bB, smem_u32(&Vs[krow * QO_STRIDE + col0 + 16 + ((lane >> 4) << 3)]));
                ldm_x2t(bC, smem_u32(&Vs[krow * QO_STRIDE + col0 + 32]));
                uint32_t pa[4];
                pa[0] = f2h2(w[2 * kk][0],     w[2 * kk][1]);
                pa[1] = f2h2(w[2 * kk][2],     w[2 * kk][3]);
                pa[2] = f2h2(w[2 * kk + 1][0], w[2 * kk + 1][1]);
                pa[3] = f2h2(w[2 * kk + 1][2], w[2 * kk + 1][3]);
                mma16816(oacc[0], pa, bA[0], bA[1]);
                mma16816(oacc[1], pa, bA[2], bA[3]);
                mma16816(oacc[2], pa, bB[0], bB[1]);
                mma16816(oacc[3], pa, bB[2], bB[3]);
                mma16816(oacc[4], pa, bC[0], bC[1]);
            }

            // write o over q (warp-private column slice)
            const int r0 = mrow + (lane >> 2);
            #pragma unroll
            for (int nt = 0; nt < 5; nt++) {
                const int col = col0 + nt * 8 + q2 * 2;
                *(uint32_t*)&Qo[r0 * QO_STRIDE + col] =
                    f2h2(oacc[nt][0] * inv0, oacc[nt][1] * inv0);
                *(uint32_t*)&Qo[(r0 + 8) * QO_STRIDE + col] =
                    f2h2(oacc[nt][2] * inv1, oacc[nt][3] * inv1);
            }
        }
    }
    __syncthreads();

    // ---- output projection: out = (o @ Wo^T + bias) * gamma ----
    const int wm2 = (wid >> 1) * 32;
    const int wn2 = (wid & 1) * 32;
    const int bsr = tid >> 2;
    const int bss = (tid & 3) * 8;

    #pragma unroll 1
    for (int nc = 0; nc < 5; nc++) {
        const int n0 = nc * 64;
        const __half* pb = woh + (size_t)(n0 + bsr) * 320 + bss;

        float acc[2][4][4];
        #pragma unroll
        for (int mt = 0; mt < 2; mt++)
            #pragma unroll
            for (int nt = 0; nt < 4; nt++)
                #pragma unroll
                for (int i = 0; i < 4; i++) acc[mt][nt][i] = 0.f;

        __syncthreads();
        cp16(smem_u32(&Bs[0 * 2560 + bsr * 40 + bss]), pb);
        CP_COMMIT();
        cp16(smem_u32(&Bs[1 * 2560 + bsr * 40 + bss]), pb + 32);
        CP_COMMIT();

        int buf = 0, pbuf = 2;
        #pragma unroll 1
        for (int ks = 0; ks < 10; ks++) {
            if (ks + 1 < 10) { CP_WAIT(1); } else { CP_WAIT(0); }
            __syncthreads();
            if (ks + 2 < 10) {
                cp16(smem_u32(&Bs[pbuf * 2560 + bsr * 40 + bss]), pb + (ks + 2) * 32);
                CP_COMMIT();
            }
            #pragma unroll
            for (int kk = 0; kk < 32; kk += 16) {
                const int kg = ks * 32 + kk;
                uint32_t af[2][4], bf[2][4];
                #pragma unroll
                for (int mt = 0; mt < 2; mt++)
                    ldm_x4(af[mt], smem_u32(&Qo[(wm2 + mt * 16 + (lane & 15)) * QO_STRIDE
                                                + kg + ((lane >> 4) & 1) * 8]));
                #pragma unroll
                for (int nh = 0; nh < 2; nh++)
                    ldm_x4(bf[nh], smem_u32(&Bs[buf * 2560
                                                + (wn2 + nh * 16 + (lane & 7) + ((lane >> 4) << 3)) * 40
                                                + kk + ((lane >> 3) & 1) * 8]));
                #pragma unroll
                for (int mt = 0; mt < 2; mt++)
                    #pragma unroll
                    for (int nt = 0; nt < 4; nt++)
                        mma16816(acc[mt][nt], af[mt],
                                 bf[nt >> 1][(nt & 1) * 2], bf[nt >> 1][(nt & 1) * 2 + 1]);
            }
            buf  = (buf  == 2) ? 0 : buf  + 1;
            pbuf = (pbuf == 2) ? 0 : pbuf + 1;
        }

        #pragma unroll
        for (int nt = 0; nt < 4; nt++) {
            const int n = n0 + wn2 + nt * 8 + (lane & 3) * 2;
            const float g0 = __ldg(&gamma[n]);
            const float g1 = __ldg(&gamma[n + 1]);
            const float b0v = __ldg(&bias[n]);
            const float b1v = __ldg(&bias[n + 1]);
            #pragma unroll
            for (int mt = 0; mt < 2; mt++) {
                const size_t row = (size_t)b * NQ_ + m0 + wm2 + mt * 16 + (lane >> 2);
                float2 p0, p1;
                p0.x = (acc[mt][nt][0] + b0v) * g0;
                p0.y = (acc[mt][nt][1] + b1v) * g1;
                p1.x = (acc[mt][nt][2] + b0v) * g0;
                p1.y = (acc[mt][nt][3] + b1v) * g1;
                *(float2*)(out + row * 320 + n)       = p0;
                *(float2*)(out + (row + 8) * 320 + n) = p1;
            }
        }
    }
}

// ---------------------------------------------------------------------------
// Launch
// ---------------------------------------------------------------------------
extern "C" void kernel_launch(void* const* d_in, const int* in_sizes, int n_in,
                              void* d_out, int out_size)
{
    (void)in_sizes; (void)n_in; (void)out_size;
    const float* x   = (const float*)d_in[0];
    const float* ctx = (const float*)d_in[1];
    const float* Wq  = (const float*)d_in[2];
    const float* Wk  = (const float*)d_in[3];
    const float* Wv  = (const float*)d_in[4];
    const float* Wo  = (const float*)d_in[5];
    const float* bo  = (const float*)d_in[6];
    const float* gq  = (const float*)d_in[7];
    const float* gk  = (const float*)d_in[8];
    const float* gv  = (const float*)d_in[9];
    const float* go  = (const float*)d_in[10];
    float* out = (float*)d_out;

    __half *xh, *ch, *qh, *kh, *vh, *wqh, *wkh, *wvh, *woh;
    cudaGetSymbolAddress((void**)&xh,  g_xh);
    cudaGetSymbolAddress((void**)&ch,  g_ch);
    cudaGetSymbolAddress((void**)&qh,  g_qh);
    cudaGetSymbolAddress((void**)&kh,  g_kh);
    cudaGetSymbolAddress((void**)&vh,  g_vh);
    cudaGetSymbolAddress((void**)&wqh, g_wqh);
    cudaGetSymbolAddress((void**)&wkh, g_wkh);
    cudaGetSymbolAddress((void**)&wvh, g_wvh);
    cudaGetSymbolAddress((void**)&woh, g_woh);

    cudaFuncSetAttribute(gemm_hmma_t<10, true>, cudaFuncAttributeMaxDynamicSharedMemorySize, GSMEM);
    cudaFuncSetAttribute(gemm_hmma_t<24, true>, cudaFuncAttributeMaxDynamicSharedMemorySize, GSMEM);
    cudaFuncSetAttribute(attn_oproj, cudaFuncAttributeMaxDynamicSharedMemorySize, AO_SMEM);

    const int Mq  = B_ * NQ_;   // 131072
    const int Mkv = B_ * NK_;   // 2464

    dim3 thr(128);
    dim3 grid_q (320 / GTN, (Mq + GTM - 1) / GTM);       // (5, 683)
    dim3 grid_kv(320 / GTN, (Mkv + GTM - 1) / GTM);      // (5, 13)
    dim3 grid_ao(NQ_ / 128, B_);                         // (32, 32)

    // fp32 -> fp16 conversions
    f2h_kernel<<<4096, 256>>>(x,   xh,  Mq * QDIM_ / 4);
    f2h_kernel<<<1024, 256>>>(ctx, ch,  Mkv * CDIM_ / 4);
    f2h_kernel<<<64,   256>>>(Wq,  wqh, INNER_ * QDIM_ / 4);
    f2h_kernel<<<128,  256>>>(Wk,  wkh, INNER_ * CDIM_ / 4);
    f2h_kernel<<<128,  256>>>(Wv,  wvh, INNER_ * CDIM_ / 4);
    f2h_kernel<<<64,   256>>>(Wo,  woh, QDIM_ * INNER_ / 4);

    // K/V projections (K=768, fp16 out)
    gemm_hmma_t<24, true><<<grid_kv, thr, GSMEM>>>(ch, wkh, gk, nullptr, kh, Mkv);
    gemm_hmma_t<24, true><<<grid_kv, thr, GSMEM>>>(ch, wvh, gv, nullptr, vh, Mkv);

    // Q projection (K=320, fp16 out)
    gemm_hmma_t<10, true><<<grid_q, thr, GSMEM>>>(xh, wqh, gq, nullptr, qh, Mq);

    // fused attention + output projection
    attn_oproj<<<grid_ao, 256, AO_SMEM>>>(qh, kh, vh, woh, go, bo, out);
}

// round 16
// speedup vs baseline: 1.4161x; 1.0813x over previous
#include <cuda_runtime.h>
#include <cuda_fp16.h>
#include <cstdint>
#include <math.h>

// ---------------------------------------------------------------------------
// Problem constants
// ---------------------------------------------------------------------------
#define B_     32
#define NQ_    4096
#define NK_    77
#define HEADS_ 8
#define DH_    40
#define INNER_ 320      // HEADS*DH
#define QDIM_  320
#define CDIM_  768

// Scratch (device globals: allocation-free per harness rules)
__device__ __half g_xh[(size_t)B_ * NQ_ * QDIM_];
__device__ __half g_ch[(size_t)B_ * NK_ * CDIM_];
__device__ __half g_qh[(size_t)B_ * NQ_ * INNER_];
__device__ __half g_kh[(size_t)B_ * NK_ * INNER_];
__device__ __half g_vh[(size_t)B_ * NK_ * INNER_];
__device__ __half g_wqh[INNER_ * QDIM_];
__device__ __half g_wkh[INNER_ * CDIM_];
__device__ __half g_wvh[INNER_ * CDIM_];
__device__ __half g_woh[QDIM_ * INNER_];

// ---------------------------------------------------------------------------
// Helpers
// ---------------------------------------------------------------------------
__device__ __forceinline__ uint32_t smem_u32(const void* p) {
    uint32_t a;
    asm("{ .reg .u64 t; cvta.to.shared.u64 t, %1; cvt.u32.u64 %0, t; }"
        : "=r"(a) : "l"(p));
    return a;
}
__device__ __forceinline__ void cp16(uint32_t dst, const void* src) {
    asm volatile("cp.async.cg.shared.global [%0], [%1], 16;" :: "r"(dst), "l"(src));
}
#define CP_COMMIT() asm volatile("cp.async.commit_group;" ::: "memory")
#define CP_WAIT(N)  asm volatile("cp.async.wait_group %0;" :: "n"(N) : "memory")

__device__ __forceinline__ void ldm_x4(uint32_t* r, uint32_t addr) {
    asm volatile("ldmatrix.sync.aligned.m8n8.x4.shared.b16 {%0,%1,%2,%3}, [%4];"
        : "=r"(r[0]), "=r"(r[1]), "=r"(r[2]), "=r"(r[3]) : "r"(addr));
}
__device__ __forceinline__ void ldm_x2(uint32_t* r, uint32_t addr) {
    asm volatile("ldmatrix.sync.aligned.m8n8.x2.shared.b16 {%0,%1}, [%2];"
        : "=r"(r[0]), "=r"(r[1]) : "r"(addr));
}
__device__ __forceinline__ void ldm_x4t(uint32_t* r, uint32_t addr) {
    asm volatile("ldmatrix.sync.aligned.m8n8.x4.trans.shared.b16 {%0,%1,%2,%3}, [%4];"
        : "=r"(r[0]), "=r"(r[1]), "=r"(r[2]), "=r"(r[3]) : "r"(addr));
}
__device__ __forceinline__ void ldm_x2t(uint32_t* r, uint32_t addr) {
    asm volatile("ldmatrix.sync.aligned.m8n8.x2.trans.shared.b16 {%0,%1}, [%2];"
        : "=r"(r[0]), "=r"(r[1]) : "r"(addr));
}
__device__ __forceinline__ void mma16816(float* c, const uint32_t* a,
                                         uint32_t b0, uint32_t b1) {
    asm volatile("mma.sync.aligned.m16n8k16.row.col.f32.f16.f16.f32 "
        "{%0,%1,%2,%3}, {%4,%5,%6,%7}, {%8,%9}, {%0,%1,%2,%3};"
        : "+f"(c[0]), "+f"(c[1]), "+f"(c[2]), "+f"(c[3])
        : "r"(a[0]), "r"(a[1]), "r"(a[2]), "r"(a[3]), "r"(b0), "r"(b1));
}
__device__ __forceinline__ void mma16808(float* c, const uint32_t* a, uint32_t b0) {
    asm volatile("mma.sync.aligned.m16n8k8.row.col.f32.f16.f16.f32 "
        "{%0,%1,%2,%3}, {%4,%5}, {%6}, {%0,%1,%2,%3};"
        : "+f"(c[0]), "+f"(c[1]), "+f"(c[2]), "+f"(c[3])
        : "r"(a[0]), "r"(a[1]), "r"(b0));
}
__device__ __forceinline__ unsigned f2h2(float a, float b) {
    __half2 h = __floats2half2_rn(a, b);
    return *reinterpret_cast<unsigned*>(&h);
}

// ---------------------------------------------------------------------------
// fp32 -> fp16 conversions
// ---------------------------------------------------------------------------
__global__ void f2h_kernel(const float* __restrict__ src,
                           __half* __restrict__ dst, int n4)
{
    int stride = gridDim.x * blockDim.x;
    for (int i = blockIdx.x * blockDim.x + threadIdx.x; i < n4; i += stride) {
        float4 f = ((const float4*)src)[i];
        uint2 u;
        u.x = f2h2(f.x, f.y);
        u.y = f2h2(f.z, f.w);
        ((uint2*)dst)[i] = u;
    }
}

// One launch converting 5 arrays (ctx + 4 weights), selected by blockIdx.y.
__global__ void f2h_multi(const float* s0, __half* d0, int n0,
                          const float* s1, __half* d1, int n1,
                          const float* s2, __half* d2, int n2,
                          const float* s3, __half* d3, int n3,
                          const float* s4, __half* d4, int n4c)
{
    const float* s; __half* d; int n;
    switch (blockIdx.y) {
        case 0: s = s0; d = d0; n = n0;  break;
        case 1: s = s1; d = d1; n = n1;  break;
        case 2: s = s2; d = d2; n = n2;  break;
        case 3: s = s3; d = d3; n = n3;  break;
        default: s = s4; d = d4; n = n4c; break;
    }
    int stride = gridDim.x * blockDim.x;
    for (int i = blockIdx.x * blockDim.x + threadIdx.x; i < n; i += stride) {
        float4 f = ((const float4*)s)[i];
        uint2 u;
        u.x = f2h2(f.x, f.y);
        u.y = f2h2(f.z, f.w);
        ((uint2*)d)[i] = u;
    }
}

// ---------------------------------------------------------------------------
// HMMA fp16 GEMM body (runtime ksteps):  C = (A@W^T)*gamma  (fp16 out)
//   CTA 192m x 64n, 128 threads = 4 warps, warp tile 48m x 64n.
//   3-stage cp.async pipeline, 3 CTAs/SM.
// ---------------------------------------------------------------------------
#define GTM 192
#define GTN 64
#define HROW 40
#define AS_STG (GTM * HROW)
#define BS_STG (GTN * HROW)
#define GSMEM ((3 * AS_STG + 3 * BS_STG) * 2)   // 61440 B

__device__ __forceinline__ void gemm_body(
    const __half* __restrict__ A, const __half* __restrict__ W,
    const float* __restrict__ gamma, __half* __restrict__ C,
    int M, int ksteps, int m0, int n0, __half* dsm)
{
    const int KD = ksteps * 32;
    __half (*As)[GTM][HROW] = (__half(*)[GTM][HROW])dsm;
    __half (*Bs)[GTN][HROW] = (__half(*)[GTN][HROW])(dsm + 3 * AS_STG);

    const int tid  = threadIdx.x;
    const int lane = tid & 31;
    const int wm   = (tid >> 5) * 48;

    const int srow = tid >> 2;
    const int scol = (tid & 3) * 8;
    int rowA[6];
    #pragma unroll
    for (int i = 0; i < 6; i++) rowA[i] = min(m0 + srow + 32 * i, M - 1);

    float acc[3][8][4];
    #pragma unroll
    for (int mt = 0; mt < 3; mt++)
        #pragma unroll
        for (int nt = 0; nt < 8; nt++)
            #pragma unroll
            for (int i = 0; i < 4; i++) acc[mt][nt][i] = 0.f;

    #pragma unroll
    for (int st = 0; st < 2; st++) {
        const int k0 = st * 32;
        #pragma unroll
        for (int i = 0; i < 6; i++)
            cp16(smem_u32(&As[st][srow + 32 * i][scol]),
                 A + (size_t)rowA[i] * KD + k0 + scol);
        #pragma unroll
        for (int i = 0; i < 2; i++)
            cp16(smem_u32(&Bs[st][srow + 32 * i][scol]),
                 W + (size_t)(n0 + srow + 32 * i) * KD + k0 + scol);
        CP_COMMIT();
    }

    int buf = 0, pbuf = 2;
    #pragma unroll 1
    for (int ks = 0; ks < ksteps; ks++) {
        if (ks + 1 < ksteps) { CP_WAIT(1); } else { CP_WAIT(0); }
        __syncthreads();
        if (ks + 2 < ksteps) {
            const int k0 = (ks + 2) * 32;
            #pragma unroll
            for (int i = 0; i < 6; i++)
                cp16(smem_u32(&As[pbuf][srow + 32 * i][scol]),
                     A + (size_t)rowA[i] * KD + k0 + scol);
            #pragma unroll
            for (int i = 0; i < 2; i++)
                cp16(smem_u32(&Bs[pbuf][srow + 32 * i][scol]),
                     W + (size_t)(n0 + srow + 32 * i) * KD + k0 + scol);
            CP_COMMIT();
        }

        #pragma unroll
        for (int kk = 0; kk < 32; kk += 16) {
            uint32_t af[3][4];
            #pragma unroll
            for (int mt = 0; mt < 3; mt++)
                ldm_x4(af[mt], smem_u32(&As[buf][wm + mt * 16 + (lane & 15)]
                                             [kk + ((lane >> 4) & 1) * 8]));
            #pragma unroll
            for (int nh = 0; nh < 4; nh++) {
                uint32_t bf[4];
                ldm_x4(bf, smem_u32(&Bs[buf][nh * 16 + (lane & 7) + ((lane >> 4) << 3)]
                                         [kk + ((lane >> 3) & 1) * 8]));
                #pragma unroll
                for (int mt = 0; mt < 3; mt++) {
                    mma16816(acc[mt][nh * 2],     af[mt], bf[0], bf[1]);
                    mma16816(acc[mt][nh * 2 + 1], af[mt], bf[2], bf[3]);
                }
            }
        }

        buf  = (buf  == 2) ? 0 : buf  + 1;
        pbuf = (pbuf == 2) ? 0 : pbuf + 1;
    }

    #pragma unroll
    for (int nt = 0; nt < 8; nt++) {
        const int n = n0 + nt * 8 + (lane & 3) * 2;
        const float g0 = __ldg(&gamma[n]);
        const float g1 = __ldg(&gamma[n + 1]);
        #pragma unroll
        for (int mt = 0; mt < 3; mt++) {
            const int r0 = m0 + wm + mt * 16 + (lane >> 2);
            if (r0 < M)
                *(uint32_t*)(C + (size_t)r0 * 320 + n) =
                    f2h2(acc[mt][nt][0] * g0, acc[mt][nt][1] * g1);
            if (r0 + 8 < M)
                *(uint32_t*)(C + (size_t)(r0 + 8) * 320 + n) =
                    f2h2(acc[mt][nt][2] * g0, acc[mt][nt][3] * g1);
        }
    }
}

// All three projections (K, V, Q) in ONE launch.
//   blocks [0, 65)    : K-proj tiles  (5 n x 13 m, ksteps=24)
//   blocks [65, 130)  : V-proj tiles
//   blocks [130, 3545): Q-proj tiles  (5 n x 683 m, ksteps=10)
__global__ void __launch_bounds__(128, 3)
gemm_mega(const __half* __restrict__ xh, const __half* __restrict__ ch,
          const __half* __restrict__ wq, const __half* __restrict__ wk,
          const __half* __restrict__ wv,
          const float* __restrict__ gq, const float* __restrict__ gk,
          const float* __restrict__ gv,
          __half* __restrict__ qh, __half* __restrict__ kh,
          __half* __restrict__ vh)
{
    extern __shared__ __half dsm[];
    const int bid = blockIdx.x;
    if (bid < 130) {
        const int z = bid / 65;            // 0: K-proj, 1: V-proj
        const int t = bid % 65;
        const int n0 = (t % 5) * GTN;
        const int m0 = (t / 5) * GTM;
        gemm_body(ch, z ? wv : wk, z ? gv : gk, z ? vh : kh,
                  B_ * NK_, 24, m0, n0, dsm);
    } else {
        const int t = bid - 130;
        const int n0 = (t % 5) * GTN;
        const int m0 = (t / 5) * GTM;
        gemm_body(xh, wq, gq, qh, B_ * NQ_, 10, m0, n0, dsm);
    }
}

// ---------------------------------------------------------------------------
// Fused attention + output projection (R12-proven version, unchanged).
//   CTA: (b, 128-query tile), 256 threads = 8 warps = 8 heads.
// ---------------------------------------------------------------------------
#define QO_STRIDE 328
#define AO_QO   0
#define AO_KS   (128 * QO_STRIDE)                 // 41984
#define AO_VS   (AO_KS + 80 * QO_STRIDE)          // 68224
#define AO_BS   (AO_VS + 80 * QO_STRIDE)          // 94464
#define AO_SMEM ((AO_BS + 3 * 64 * 40) * 2)       // 204288 B

__global__ void __launch_bounds__(256, 1)
attn_oproj(const __half* __restrict__ qh, const __half* __restrict__ kh,
           const __half* __restrict__ vh, const __half* __restrict__ woh,
           const float* __restrict__ gamma, const float* __restrict__ bias,
           float* __restrict__ out)
{
    extern __shared__ __half dsm[];
    __half* Qo = dsm + AO_QO;     // [128][328]
    __half* Ks = dsm + AO_KS;     // [80][328]
    __half* Vs = dsm + AO_VS;     // [80][328]
    __half* Bs = dsm + AO_BS;     // [3][64][40]

    const int b   = blockIdx.y;
    const int m0  = blockIdx.x * 128;
    const int tid = threadIdx.x, lane = tid & 31, wid = tid >> 5;

    const __half* qbase = qh + ((size_t)b * NQ_ + m0) * INNER_;
    const __half* kbase = kh + (size_t)b * NK_ * INNER_;
    const __half* vbase = vh + (size_t)b * NK_ * INNER_;

    // ---- stage q tile: 128 rows x 40 chunks ----
    #pragma unroll
    for (int i = 0; i < 20; i++) {
        int c = tid + i * 256;
        int r = c / 40, s = c % 40;
        cp16(smem_u32(&Qo[r * QO_STRIDE + s * 8]), qbase + (size_t)r * INNER_ + s * 8);
    }
    // ---- stage K, V: 77 rows x 40 chunks each ----
    for (int c = tid; c < 3080; c += 256) {
        int r = c / 40, s = c % 40;
        cp16(smem_u32(&Ks[r * QO_STRIDE + s * 8]), kbase + (size_t)r * INNER_ + s * 8);
        cp16(smem_u32(&Vs[r * QO_STRIDE + s * 8]), vbase + (size_t)r * INNER_ + s * 8);
    }
    CP_COMMIT();
    // zero key-pad rows 77-79 (disjoint from cp.async targets)
    if (tid < 120) {
        int r = 77 + tid / 40, s = tid % 40;
        const uint4 z4 = make_uint4(0, 0, 0, 0);
        *(uint4*)&Ks[r * QO_STRIDE + s * 8] = z4;
        *(uint4*)&Vs[r * QO_STRIDE + s * 8] = z4;
    }
    CP_WAIT(0);
    __syncthreads();

    // ---- attention: warp `wid` = head, all 128 queries, dh-exact ----
    {
        const int col0 = wid * DH_;
        const float scale = 0.15811388300841897f;   // 40^-0.5
        const int q2 = lane & 3;
        const bool ok0 = (72 + q2 * 2)     < 77;
        const bool ok1 = (72 + q2 * 2 + 1) < 77;

        #pragma unroll 1
        for (int mt = 0; mt < 8; mt++) {
            const int mrow = mt * 16;
            float w[10][4];
            #pragma unroll
            for (int nt = 0; nt < 10; nt++)
                #pragma unroll
                for (int i = 0; i < 4; i++) w[nt][i] = 0.f;

            // S = q K^T
            #pragma unroll
            for (int ksi = 0; ksi < 2; ksi++) {
                uint32_t af[4];
                ldm_x4(af, smem_u32(&Qo[(mrow + (lane & 15)) * QO_STRIDE
                                        + col0 + ksi * 16 + ((lane >> 4) & 1) * 8]));
                #pragma unroll
                for (int nh = 0; nh < 5; nh++) {
                    uint32_t bf[4];
                    ldm_x4(bf, smem_u32(&Ks[(nh * 16 + (lane & 7) + ((lane >> 4) << 3)) * QO_STRIDE
                                            + col0 + ksi * 16 + ((lane >> 3) & 1) * 8]));
                    mma16816(w[nh * 2],     af, bf[0], bf[1]);
                    mma16816(w[nh * 2 + 1], af, bf[2], bf[3]);
                }
            }
            {   // k8 tail (dh 32..39)
                uint32_t a8[2];
                ldm_x2(a8, smem_u32(&Qo[(mrow + (lane & 15)) * QO_STRIDE + col0 + 32]));
                #pragma unroll
                for (int nh = 0; nh < 5; nh++) {
                    uint32_t b8[2];
                    ldm_x2(b8, smem_u32(&Ks[(nh * 16 + (lane & 15)) * QO_STRIDE + col0 + 32]));
                    mma16808(w[nh * 2],     a8, b8[0]);
                    mma16808(w[nh * 2 + 1], a8, b8[1]);
                }
            }

            // softmax weights + row sums
            float s0 = 0.f, s1 = 0.f;
            #pragma unroll
            for (int nt = 0; nt < 10; nt++) {
                float e0 = __expf(w[nt][0] * scale);
                float e1 = __expf(w[nt][1] * scale);
                float e2 = __expf(w[nt][2] * scale);
                float e3 = __expf(w[nt][3] * scale);
                if (nt == 9) {
                    if (!ok0) { e0 = 0.f; e2 = 0.f; }
                    if (!ok1) { e1 = 0.f; e3 = 0.f; }
                }
                w[nt][0] = e0; w[nt][1] = e1;
                w[nt][2] = e2; w[nt][3] = e3;
                s0 += e0 + e1;
                s1 += e2 + e3;
            }
            s0 += __shfl_xor_sync(0xffffffffu, s0, 1);
            s0 += __shfl_xor_sync(0xffffffffu, s0, 2);
            s1 += __shfl_xor_sync(0xffffffffu, s1, 1);
            s1 += __shfl_xor_sync(0xffffffffu, s1, 2);
            const float inv0 = 1.f / s0;
            const float inv1 = 1.f / s1;

            // O = P V
            float oacc[5][4];
            #pragma unroll
            for (int nt = 0; nt < 5; nt++)
                #pragma unroll
                for (int i = 0; i < 4; i++) oacc[nt][i] = 0.f;

            #pragma unroll
            for (int kk = 0; kk < 5; kk++) {
                const int krow = kk * 16 + (lane & 7) + ((lane >> 3) & 1) * 8;
                uint32_t bA[4], bB[4], bC[2];
                ldm_x4t(bA, smem_u32(&Vs[krow * QO_STRIDE + col0 + ((lane >> 4) << 3)]));
                ldm_x4t(bB, smem_u32(&Vs[krow * QO_STRIDE + col0 + 16 + ((lane >> 4) << 3)]));
                ldm_x2t(bC, smem_u32(&Vs[krow * QO_STRIDE + col0 + 32]));
                uint32_t pa[4];
                pa[0] = f2h2(w[2 * kk][0],     w[2 * kk][1]);
                pa[1] = f2h2(w[2 * kk][2],     w[2 * kk][3]);
                pa[2] = f2h2(w[2 * kk + 1][0], w[2 * kk + 1][1]);
                pa[3] = f2h2(w[2 * kk + 1][2], w[2 * kk + 1][3]);
                mma16816(oacc[0], pa, bA[0], bA[1]);
                mma16816(oacc[1], pa, bA[2], bA[3]);
                mma16816(oacc[2], pa, bB[0], bB[1]);
                mma16816(oacc[3], pa, bB[2], bB[3]);
                mma16816(oacc[4], pa, bC[0], bC[1]);
            }

            // write o over q (warp-private column slice)
            const int r0 = mrow + (lane >> 2);
            #pragma unroll
            for (int nt = 0; nt < 5; nt++) {
                const int col = col0 + nt * 8 + q2 * 2;
                *(uint32_t*)&Qo[r0 * QO_STRIDE + col] =
                    f2h2(oacc[nt][0] * inv0, oacc[nt][1] * inv0);
                *(uint32_t*)&Qo[(r0 + 8) * QO_STRIDE + col] =
                    f2h2(oacc[nt][2] * inv1, oacc[nt][3] * inv1);
            }
        }
    }
    __syncthreads();

    // ---- output projection: out = (o @ Wo^T + bias) * gamma ----
    const int wm2 = (wid >> 1) * 32;
    const int wn2 = (wid & 1) * 32;
    const int bsr = tid >> 2;
    const int bss = (tid & 3) * 8;

    #pragma unroll 1
    for (int nc = 0; nc < 5; nc++) {
        const int n0 = nc * 64;
        const __half* pb = woh + (size_t)(n0 + bsr) * 320 + bss;

        float acc[2][4][4];
        #pragma unroll
        for (int mt = 0; mt < 2; mt++)
            #pragma unroll
            for (int nt = 0; nt < 4; nt++)
                #pragma unroll
                for (int i = 0; i < 4; i++) acc[mt][nt][i] = 0.f;

        __syncthreads();
        cp16(smem_u32(&Bs[0 * 2560 + bsr * 40 + bss]), pb);
        CP_COMMIT();
        cp16(smem_u32(&Bs[1 * 2560 + bsr * 40 + bss]), pb + 32);
        CP_COMMIT();

        int buf = 0, pbuf = 2;
        #pragma unroll 1
        for (int ks = 0; ks < 10; ks++) {
            if (ks + 1 < 10) { CP_WAIT(1); } else { CP_WAIT(0); }
            __syncthreads();
            if (ks + 2 < 10) {
                cp16(smem_u32(&Bs[pbuf * 2560 + bsr * 40 + bss]), pb + (ks + 2) * 32);
                CP_COMMIT();
            }
            #pragma unroll
            for (int kk = 0; kk < 32; kk += 16) {
                const int kg = ks * 32 + kk;
                uint32_t af[2][4], bf[2][4];
                #pragma unroll
                for (int mt = 0; mt < 2; mt++)
                    ldm_x4(af[mt], smem_u32(&Qo[(wm2 + mt * 16 + (lane & 15)) * QO_STRIDE
                                                + kg + ((lane >> 4) & 1) * 8]));
                #pragma unroll
                for (int nh = 0; nh < 2; nh++)
                    ldm_x4(bf[nh], smem_u32(&Bs[buf * 2560
                                                + (wn2 + nh * 16 + (lane & 7) + ((lane >> 4) << 3)) * 40
                                                + kk + ((lane >> 3) & 1) * 8]));
                #pragma unroll
                for (int mt = 0; mt < 2; mt++)
                    #pragma unroll
                    for (int nt = 0; nt < 4; nt++)
                        mma16816(acc[mt][nt], af[mt],
                                 bf[nt >> 1][(nt & 1) * 2], bf[nt >> 1][(nt & 1) * 2 + 1]);
            }
            buf  = (buf  == 2) ? 0 : buf  + 1;
            pbuf = (pbuf == 2) ? 0 : pbuf + 1;
        }

        #pragma unroll
        for (int nt = 0; nt < 4; nt++) {
            const int n = n0 + wn2 + nt * 8 + (lane & 3) * 2;
            const float g0 = __ldg(&gamma[n]);
            const float g1 = __ldg(&gamma[n + 1]);
            const float b0v = __ldg(&bias[n]);
            const float b1v = __ldg(&bias[n + 1]);
            #pragma unroll
            for (int mt = 0; mt < 2; mt++) {
                const size_t row = (size_t)b * NQ_ + m0 + wm2 + mt * 16 + (lane >> 2);
                float2 p0, p1;
                p0.x = (acc[mt][nt][0] + b0v) * g0;
                p0.y = (acc[mt][nt][1] + b1v) * g1;
                p1.x = (acc[mt][nt][2] + b0v) * g0;
                p1.y = (acc[mt][nt][3] + b1v) * g1;
                *(float2*)(out + row * 320 + n)       = p0;
                *(float2*)(out + (row + 8) * 320 + n) = p1;
            }
        }
    }
}

// ---------------------------------------------------------------------------
// Launch
// ---------------------------------------------------------------------------
extern "C" void kernel_launch(void* const* d_in, const int* in_sizes, int n_in,
                              void* d_out, int out_size)
{
    (void)in_sizes; (void)n_in; (void)out_size;
    const float* x   = (const float*)d_in[0];
    const float* ctx = (const float*)d_in[1];
    const float* Wq  = (const float*)d_in[2];
    const float* Wk  = (const float*)d_in[3];
    const float* Wv  = (const float*)d_in[4];
    const float* Wo  = (const float*)d_in[5];
    const float* bo  = (const float*)d_in[6];
    const float* gq  = (const float*)d_in[7];
    const float* gk  = (const float*)d_in[8];
    const float* gv  = (const float*)d_in[9];
    const float* go  = (const float*)d_in[10];
    float* out = (float*)d_out;

    __half *xh, *ch, *qh, *kh, *vh, *wqh, *wkh, *wvh, *woh;
    cudaGetSymbolAddress((void**)&xh,  g_xh);
    cudaGetSymbolAddress((void**)&ch,  g_ch);
    cudaGetSymbolAddress((void**)&qh,  g_qh);
    cudaGetSymbolAddress((void**)&kh,  g_kh);
    cudaGetSymbolAddress((void**)&vh,  g_vh);
    cudaGetSymbolAddress((void**)&wqh, g_wqh);
    cudaGetSymbolAddress((void**)&wkh, g_wkh);
    cudaGetSymbolAddress((void**)&wvh, g_wvh);
    cudaGetSymbolAddress((void**)&woh, g_woh);

    cudaFuncSetAttribute(gemm_mega,  cudaFuncAttributeMaxDynamicSharedMemorySize, GSMEM);
    cudaFuncSetAttribute(attn_oproj, cudaFuncAttributeMaxDynamicSharedMemorySize, AO_SMEM);

    const int Mq = B_ * NQ_;   // 131072

    // 1) conversions: big x; ctx + 4 weights in one launch
    f2h_kernel<<<4096, 256>>>(x, xh, Mq * QDIM_ / 4);
    f2h_multi<<<dim3(512, 5), 256>>>(
        ctx, ch,  B_ * NK_ * CDIM_ / 4,
        Wq,  wqh, INNER_ * QDIM_ / 4,
        Wk,  wkh, INNER_ * CDIM_ / 4,
        Wv,  wvh, INNER_ * CDIM_ / 4,
        Wo,  woh, QDIM_ * INNER_ / 4);

    // 2) all three projections in one launch (130 KV tiles + 3415 Q tiles)
    gemm_mega<<<3545, 128, GSMEM>>>(xh, ch, wqh, wkh, wvh, gq, gk, gv,
                                    qh, kh, vh);

    // 3) fused attention + output projection
    attn_oproj<<<dim3(NQ_ / 128, B_), 256, AO_SMEM>>>(qh, kh, vh, woh, go, bo, out);
}

// round 17
// speedup vs baseline: 1.4403x; 1.0171x over previous
#include <cuda_runtime.h>
#include <cuda_fp16.h>
#include <cstdint>
#include <math.h>

// ---------------------------------------------------------------------------
// Problem constants
// ---------------------------------------------------------------------------
#define B_     32
#define NQ_    4096
#define NK_    77
#define HEADS_ 8
#define DH_    40
#define INNER_ 320      // HEADS*DH
#define QDIM_  320
#define CDIM_  768

// Scratch (device globals: allocation-free per harness rules)
__device__ __half g_xh[(size_t)B_ * NQ_ * QDIM_];
__device__ __half g_ch[(size_t)B_ * NK_ * CDIM_];
__device__ __half g_qh[(size_t)B_ * NQ_ * INNER_];
__device__ __half g_oh[(size_t)B_ * NQ_ * INNER_];
__device__ __half g_kh[(size_t)B_ * NK_ * INNER_];
__device__ __half g_vh[(size_t)B_ * NK_ * INNER_];
__device__ __half g_wqh[INNER_ * QDIM_];
__device__ __half g_wkh[INNER_ * CDIM_];
__device__ __half g_wvh[INNER_ * CDIM_];
__device__ __half g_woh[QDIM_ * INNER_];

// ---------------------------------------------------------------------------
// Helpers
// ---------------------------------------------------------------------------
__device__ __forceinline__ uint32_t smem_u32(const void* p) {
    uint32_t a;
    asm("{ .reg .u64 t; cvta.to.shared.u64 t, %1; cvt.u32.u64 %0, t; }"
        : "=r"(a) : "l"(p));
    return a;
}
__device__ __forceinline__ void cp16(uint32_t dst, const void* src) {
    asm volatile("cp.async.cg.shared.global [%0], [%1], 16;" :: "r"(dst), "l"(src));
}
#define CP_COMMIT() asm volatile("cp.async.commit_group;" ::: "memory")
#define CP_WAIT(N)  asm volatile("cp.async.wait_group %0;" :: "n"(N) : "memory")

__device__ __forceinline__ void ldm_x4(uint32_t* r, uint32_t addr) {
    asm volatile("ldmatrix.sync.aligned.m8n8.x4.shared.b16 {%0,%1,%2,%3}, [%4];"
        : "=r"(r[0]), "=r"(r[1]), "=r"(r[2]), "=r"(r[3]) : "r"(addr));
}
__device__ __forceinline__ void ldm_x4t(uint32_t* r, uint32_t addr) {
    asm volatile("ldmatrix.sync.aligned.m8n8.x4.trans.shared.b16 {%0,%1,%2,%3}, [%4];"
        : "=r"(r[0]), "=r"(r[1]), "=r"(r[2]), "=r"(r[3]) : "r"(addr));
}
__device__ __forceinline__ void ldm_x2t(uint32_t* r, uint32_t addr) {
    asm volatile("ldmatrix.sync.aligned.m8n8.x2.trans.shared.b16 {%0,%1}, [%2];"
        : "=r"(r[0]), "=r"(r[1]) : "r"(addr));
}
__device__ __forceinline__ void mma16816(float* c, const uint32_t* a,
                                         uint32_t b0, uint32_t b1) {
    asm volatile("mma.sync.aligned.m16n8k16.row.col.f32.f16.f16.f32 "
        "{%0,%1,%2,%3}, {%4,%5,%6,%7}, {%8,%9}, {%0,%1,%2,%3};"
        : "+f"(c[0]), "+f"(c[1]), "+f"(c[2]), "+f"(c[3])
        : "r"(a[0]), "r"(a[1]), "r"(a[2]), "r"(a[3]), "r"(b0), "r"(b1));
}
__device__ __forceinline__ unsigned f2h2(float a, float b) {
    __half2 h = __floats2half2_rn(a, b);
    return *reinterpret_cast<unsigned*>(&h);
}

// ---------------------------------------------------------------------------
// fp32 -> fp16 conversions
// ---------------------------------------------------------------------------
__global__ void f2h_kernel(const float* __restrict__ src,
                           __half* __restrict__ dst, int n4)
{
    int stride = gridDim.x * blockDim.x;
    for (int i = blockIdx.x * blockDim.x + threadIdx.x; i < n4; i += stride) {
        float4 f = ((const float4*)src)[i];
        uint2 u;
        u.x = f2h2(f.x, f.y);
        u.y = f2h2(f.z, f.w);
        ((uint2*)dst)[i] = u;
    }
}

// One launch converting 5 arrays (ctx + 4 weights), selected by blockIdx.y.
__global__ void f2h_multi(const float* s0, __half* d0, int n0,
                          const float* s1, __half* d1, int n1,
                          const float* s2, __half* d2, int n2,
                          const float* s3, __half* d3, int n3,
                          const float* s4, __half* d4, int n4c)
{
    const float* s; __half* d; int n;
    switch (blockIdx.y) {
        case 0: s = s0; d = d0; n = n0;  break;
        case 1: s = s1; d = d1; n = n1;  break;
        case 2: s = s2; d = d2; n = n2;  break;
        case 3: s = s3; d = d3; n = n3;  break;
        default: s = s4; d = d4; n = n4c; break;
    }
    int stride = gridDim.x * blockDim.x;
    for (int i = blockIdx.x * blockDim.x + threadIdx.x; i < n; i += stride) {
        float4 f = ((const float4*)s)[i];
        uint2 u;
        u.x = f2h2(f.x, f.y);
        u.y = f2h2(f.z, f.w);
        ((uint2*)d)[i] = u;
    }
}

// ---------------------------------------------------------------------------
// HMMA fp16 GEMM body (runtime ksteps):  C = (A@W^T + bias)*gamma
//   CTA 192m x 64n, 128 threads = 4 warps, warp tile 48m x 64n.
//   3-stage cp.async pipeline, 3 CTAs/SM.
// ---------------------------------------------------------------------------
#define GTM 192
#define GTN 64
#define HROW 40
#define AS_STG (GTM * HROW)
#define BS_STG (GTN * HROW)
#define GSMEM ((3 * AS_STG + 3 * BS_STG) * 2)   // 61440 B

template<bool HALF_OUT>
__device__ __forceinline__ void gemm_body(
    const __half* __restrict__ A, const __half* __restrict__ W,
    const float* __restrict__ gamma, const float* __restrict__ bias,
    void* __restrict__ Cv,
    int M, int ksteps, int m0, int n0, __half* dsm)
{
    const int KD = ksteps * 32;
    __half (*As)[GTM][HROW] = (__half(*)[GTM][HROW])dsm;
    __half (*Bs)[GTN][HROW] = (__half(*)[GTN][HROW])(dsm + 3 * AS_STG);

    const int tid  = threadIdx.x;
    const int lane = tid & 31;
    const int wm   = (tid >> 5) * 48;

    const int srow = tid >> 2;
    const int scol = (tid & 3) * 8;
    int rowA[6];
    #pragma unroll
    for (int i = 0; i < 6; i++) rowA[i] = min(m0 + srow + 32 * i, M - 1);

    float acc[3][8][4];
    #pragma unroll
    for (int mt = 0; mt < 3; mt++)
        #pragma unroll
        for (int nt = 0; nt < 8; nt++)
            #pragma unroll
            for (int i = 0; i < 4; i++) acc[mt][nt][i] = 0.f;

    #pragma unroll
    for (int st = 0; st < 2; st++) {
        const int k0 = st * 32;
        #pragma unroll
        for (int i = 0; i < 6; i++)
            cp16(smem_u32(&As[st][srow + 32 * i][scol]),
                 A + (size_t)rowA[i] * KD + k0 + scol);
        #pragma unroll
        for (int i = 0; i < 2; i++)
            cp16(smem_u32(&Bs[st][srow + 32 * i][scol]),
                 W + (size_t)(n0 + srow + 32 * i) * KD + k0 + scol);
        CP_COMMIT();
    }

    int buf = 0, pbuf = 2;
    #pragma unroll 1
    for (int ks = 0; ks < ksteps; ks++) {
        if (ks + 1 < ksteps) { CP_WAIT(1); } else { CP_WAIT(0); }
        __syncthreads();
        if (ks + 2 < ksteps) {
            const int k0 = (ks + 2) * 32;
            #pragma unroll
            for (int i = 0; i < 6; i++)
                cp16(smem_u32(&As[pbuf][srow + 32 * i][scol]),
                     A + (size_t)rowA[i] * KD + k0 + scol);
            #pragma unroll
            for (int i = 0; i < 2; i++)
                cp16(smem_u32(&Bs[pbuf][srow + 32 * i][scol]),
                     W + (size_t)(n0 + srow + 32 * i) * KD + k0 + scol);
            CP_COMMIT();
        }

        #pragma unroll
        for (int kk = 0; kk < 32; kk += 16) {
            uint32_t af[3][4];
            #pragma unroll
            for (int mt = 0; mt < 3; mt++)
                ldm_x4(af[mt], smem_u32(&As[buf][wm + mt * 16 + (lane & 15)]
                                             [kk + ((lane >> 4) & 1) * 8]));
            #pragma unroll
            for (int nh = 0; nh < 4; nh++) {
                uint32_t bf[4];
                ldm_x4(bf, smem_u32(&Bs[buf][nh * 16 + (lane & 7) + ((lane >> 4) << 3)]
                                         [kk + ((lane >> 3) & 1) * 8]));
                #pragma unroll
                for (int mt = 0; mt < 3; mt++) {
                    mma16816(acc[mt][nh * 2],     af[mt], bf[0], bf[1]);
                    mma16816(acc[mt][nh * 2 + 1], af[mt], bf[2], bf[3]);
                }
            }
        }

        buf  = (buf  == 2) ? 0 : buf  + 1;
        pbuf = (pbuf == 2) ? 0 : pbuf + 1;
    }

    #pragma unroll
    for (int nt = 0; nt < 8; nt++) {
        const int n = n0 + nt * 8 + (lane & 3) * 2;
        const float g0 = __ldg(&gamma[n]);
        const float g1 = __ldg(&gamma[n + 1]);
        const float b0 = bias ? __ldg(&bias[n])     : 0.f;
        const float b1 = bias ? __ldg(&bias[n + 1]) : 0.f;
        #pragma unroll
        for (int mt = 0; mt < 3; mt++) {
            const int r0 = m0 + wm + mt * 16 + (lane >> 2);
            float v00 = (acc[mt][nt][0] + b0) * g0;
            float v01 = (acc[mt][nt][1] + b1) * g1;
            float v10 = (acc[mt][nt][2] + b0) * g0;
            float v11 = (acc[mt][nt][3] + b1) * g1;
            if (HALF_OUT) {
                __half* C = (__half*)Cv;
                if (r0 < M)
                    *(uint32_t*)(C + (size_t)r0 * 320 + n) = f2h2(v00, v01);
                if (r0 + 8 < M)
                    *(uint32_t*)(C + (size_t)(r0 + 8) * 320 + n) = f2h2(v10, v11);
            } else {
                float* C = (float*)Cv;
                if (r0 < M) {
                    float2 p; p.x = v00; p.y = v01;
                    *(float2*)(C + (size_t)r0 * 320 + n) = p;
                }
                if (r0 + 8 < M) {
                    float2 p; p.x = v10; p.y = v11;
                    *(float2*)(C + (size_t)(r0 + 8) * 320 + n) = p;
                }
            }
        }
    }
}

// All three input projections (K, V, Q) in ONE launch.
//   blocks [0, 65)    : K-proj tiles  (5 n x 13 m, ksteps=24)
//   blocks [65, 130)  : V-proj tiles
//   blocks [130, 3545): Q-proj tiles  (5 n x 683 m, ksteps=10)
__global__ void __launch_bounds__(128, 3)
gemm_mega(const __half* __restrict__ xh, const __half* __restrict__ ch,
          const __half* __restrict__ wq, const __half* __restrict__ wk,
          const __half* __restrict__ wv,
          const float* __restrict__ gq, const float* __restrict__ gk,
          const float* __restrict__ gv,
          __half* __restrict__ qh, __half* __restrict__ kh,
          __half* __restrict__ vh)
{
    extern __shared__ __half dsm[];
    const int bid = blockIdx.x;
    if (bid < 130) {
        const int z = bid / 65;            // 0: K-proj, 1: V-proj
        const int t = bid % 65;
        const int n0 = (t % 5) * GTN;
        const int m0 = (t / 5) * GTM;
        gemm_body<true>(ch, z ? wv : wk, z ? gv : gk, nullptr,
                        z ? vh : kh, B_ * NK_, 24, m0, n0, dsm);
    } else {
        const int t = bid - 130;
        const int n0 = (t % 5) * GTN;
        const int m0 = (t / 5) * GTM;
        gemm_body<true>(xh, wq, gq, nullptr, qh, B_ * NQ_, 10, m0, n0, dsm);
    }
}

// Output projection: out = (o @ Wo^T + bias) * gamma, fp32 out.
__global__ void __launch_bounds__(128, 3)
gemm_oproj(const __half* __restrict__ oh, const __half* __restrict__ wo,
           const float* __restrict__ go, const float* __restrict__ bo,
           float* __restrict__ out)
{
    extern __shared__ __half dsm[];
    const int n0 = (blockIdx.x % 5) * GTN;
    const int m0 = (blockIdx.x / 5) * GTM;
    gemm_body<false>(oh, wo, go, bo, out, B_ * NQ_, 10, m0, n0, dsm);
}

// ---------------------------------------------------------------------------
// HMMA attention (R7-proven): per CTA 256 queries of one (b,h), 8 warps.
//   NK=77 -> padded 80.  fp16 in/out.
// ---------------------------------------------------------------------------
__device__ __forceinline__ void ldm_x2_(uint32_t* r, uint32_t addr) {
    asm volatile("ldmatrix.sync.aligned.m8n8.x2.shared.b16 {%0,%1}, [%2];"
        : "=r"(r[0]), "=r"(r[1]) : "r"(addr));
}

__global__ void __launch_bounds__(256)
attn_hmma(const __half* __restrict__ qh, const __half* __restrict__ kh,
          const __half* __restrict__ vh, __half* __restrict__ oh)
{
    __shared__ __half Qs[256][56];
    __shared__ __half Ks[80][56];
    __shared__ __half Vs[80][40];

    const int b = blockIdx.z, h = blockIdx.y;
    const int tid = threadIdx.x, lane = tid & 31, wid = tid >> 5;
    const int m0 = blockIdx.x * 256;

    const __half* qbase = qh + ((size_t)b * NQ_ + m0) * INNER_ + h * DH_;
    const __half* kbase = kh + ((size_t)b * NK_) * INNER_ + h * DH_;
    const __half* vbase = vh + ((size_t)b * NK_) * INNER_ + h * DH_;

    #pragma unroll
    for (int i = 0; i < 5; i++) {
        int c = tid + i * 256;
        int r = c / 5, s = c % 5;
        cp16(smem_u32(&Qs[r][s * 8]), qbase + (size_t)r * INNER_ + s * 8);
    }
    for (int c = tid; c < 385; c += 256) {
        int r = c / 5, s = c % 5;
        cp16(smem_u32(&Ks[r][s * 8]), kbase + (size_t)r * INNER_ + s * 8);
    }
    for (int c = tid; c < 385; c += 256) {
        int r = c / 5, s = c % 5;
        cp16(smem_u32(&Vs[r][s * 8]), vbase + (size_t)r * INNER_ + s * 8);
    }
    CP_COMMIT();

    const uint4 z4 = make_uint4(0, 0, 0, 0);
    *(uint4*)&Qs[tid][40] = z4;
    if (tid < 80) *(uint4*)&Ks[tid][40] = z4;
    if (tid < 15) {
        int r = 77 + tid / 5, s = tid % 5;
        *(uint4*)&Ks[r][s * 8] = z4;
    }
    if (tid >= 32 && tid < 47) {
        int t = tid - 32;
        int r = 77 + t / 5, s = t % 5;
        *(uint4*)&Vs[r][s * 8] = z4;
    }
    CP_WAIT(0);
    __syncthreads();

    const int wq = wid * 32;
    float w[2][10][4];
    #pragma unroll
    for (int mt = 0; mt < 2; mt++)
        #pragma unroll
        for (int nt = 0; nt < 10; nt++)
            #pragma unroll
            for (int i = 0; i < 4; i++) w[mt][nt][i] = 0.f;

    #pragma unroll
    for (int ksi = 0; ksi < 3; ksi++) {
        uint32_t af[2][4];
        #pragma unroll
        for (int mt = 0; mt < 2; mt++)
            ldm_x4(af[mt], smem_u32(&Qs[wq + mt * 16 + (lane & 15)]
                                       [ksi * 16 + ((lane >> 4) & 1) * 8]));
        #pragma unroll
        for (int nh = 0; nh < 5; nh++) {
            uint32_t bf[4];
            ldm_x4(bf, smem_u32(&Ks[nh * 16 + (lane & 7) + ((lane >> 4) << 3)]
                                   [ksi * 16 + ((lane >> 3) & 1) * 8]));
            #pragma unroll
            for (int mt = 0; mt < 2; mt++) {
                mma16816(w[mt][nh * 2],     af[mt], bf[0], bf[1]);
                mma16816(w[mt][nh * 2 + 1], af[mt], bf[2], bf[3]);
            }
        }
    }

    const float scale = 0.15811388300841897f;
    const int q2 = lane & 3;
    const bool ok0 = (72 + q2 * 2)     < 77;
    const bool ok1 = (72 + q2 * 2 + 1) < 77;
    float inv0[2], inv1[2];
    #pragma unroll
    for (int mt = 0; mt < 2; mt++) {
        float s0 = 0.f, s1 = 0.f;
        #pragma unroll
        for (int nt = 0; nt < 10; nt++) {
            float e0 = __expf(w[mt][nt][0] * scale);
            float e1 = __expf(w[mt][nt][1] * scale);
            float e2 = __expf(w[mt][nt][2] * scale);
            float e3 = __expf(w[mt][nt][3] * scale);
            if (nt == 9) {
                if (!ok0) { e0 = 0.f; e2 = 0.f; }
                if (!ok1) { e1 = 0.f; e3 = 0.f; }
            }
            w[mt][nt][0] = e0; w[mt][nt][1] = e1;
            w[mt][nt][2] = e2; w[mt][nt][3] = e3;
            s0 += e0 + e1;
            s1 += e2 + e3;
        }
        s0 += __shfl_xor_sync(0xffffffffu, s0, 1);
        s0 += __shfl_xor_sync(0xffffffffu, s0, 2);
        s1 += __shfl_xor_sync(0xffffffffu, s1, 1);
        s1 += __shfl_xor_sync(0xffffffffu, s1, 2);
        inv0[mt] = 1.f / s0;
        inv1[mt] = 1.f / s1;
    }

    float oacc[2][5][4];
    #pragma unroll
    for (int mt = 0; mt < 2; mt++)
        #pragma unroll
        for (int nt = 0; nt < 5; nt++)
            #pragma unroll
            for (int i = 0; i < 4; i++) oacc[mt][nt][i] = 0.f;

    #pragma unroll
    for (int kk = 0; kk < 5; kk++) {
        const int krow = kk * 16 + (lane & 7) + ((lane >> 3) & 1) * 8;
        uint32_t bA[4], bB[4], bC[2];
        ldm_x4t(bA, smem_u32(&Vs[krow][(lane >> 4) << 3]));
        ldm_x4t(bB, smem_u32(&Vs[krow][16 + ((lane >> 4) << 3)]));
        ldm_x2t(bC, smem_u32(&Vs[krow][32]));
        #pragma unroll
        for (int mt = 0; mt < 2; mt++) {
            uint32_t pa[4];
            pa[0] = f2h2(w[mt][2 * kk][0],     w[mt][2 * kk][1]);
            pa[1] = f2h2(w[mt][2 * kk][2],     w[mt][2 * kk][3]);
            pa[2] = f2h2(w[mt][2 * kk + 1][0], w[mt][2 * kk + 1][1]);
            pa[3] = f2h2(w[mt][2 * kk + 1][2], w[mt][2 * kk + 1][3]);
            mma16816(oacc[mt][0], pa, bA[0], bA[1]);
            mma16816(oacc[mt][1], pa, bA[2], bA[3]);
            mma16816(oacc[mt][2], pa, bB[0], bB[1]);
            mma16816(oacc[mt][3], pa, bB[2], bB[3]);
            mma16816(oacc[mt][4], pa, bC[0], bC[1]);
        }
    }

    __half* obase = oh + ((size_t)b * NQ_ + m0) * INNER_ + h * DH_;
    #pragma unroll
    for (int mt = 0; mt < 2; mt++) {
        const int r0 = wq + mt * 16 + (lane >> 2);
        #pragma unroll
        for (int nt = 0; nt < 5; nt++) {
            const int col = nt * 8 + q2 * 2;
            *(uint32_t*)(obase + (size_t)r0 * INNER_ + col) =
                f2h2(oacc[mt][nt][0] * inv0[mt], oacc[mt][nt][1] * inv0[mt]);
            *(uint32_t*)(obase + (size_t)(r0 + 8) * INNER_ + col) =
                f2h2(oacc[mt][nt][2] * inv1[mt], oacc[mt][nt][3] * inv1[mt]);
        }
    }
}

// ---------------------------------------------------------------------------
// Launch
// ---------------------------------------------------------------------------
extern "C" void kernel_launch(void* const* d_in, const int* in_sizes, int n_in,
                              void* d_out, int out_size)
{
    (void)in_sizes; (void)n_in; (void)out_size;
    const float* x   = (const float*)d_in[0];
    const float* ctx = (const float*)d_in[1];
    const float* Wq  = (const float*)d_in[2];
    const float* Wk  = (const float*)d_in[3];
    const float* Wv  = (const float*)d_in[4];
    const float* Wo  = (const float*)d_in[5];
    const float* bo  = (const float*)d_in[6];
    const float* gq  = (const float*)d_in[7];
    const float* gk  = (const float*)d_in[8];
    const float* gv  = (const float*)d_in[9];
    const float* go  = (const float*)d_in[10];
    float* out = (float*)d_out;

    __half *xh, *ch, *qh, *oh, *kh, *vh, *wqh, *wkh, *wvh, *woh;
    cudaGetSymbolAddress((void**)&xh,  g_xh);
    cudaGetSymbolAddress((void**)&ch,  g_ch);
    cudaGetSymbolAddress((void**)&qh,  g_qh);
    cudaGetSymbolAddress((void**)&oh,  g_oh);
    cudaGetSymbolAddress((void**)&kh,  g_kh);
    cudaGetSymbolAddress((void**)&vh,  g_vh);
    cudaGetSymbolAddress((void**)&wqh, g_wqh);
    cudaGetSymbolAddress((void**)&wkh, g_wkh);
    cudaGetSymbolAddress((void**)&wvh, g_wvh);
    cudaGetSymbolAddress((void**)&woh, g_woh);

    cudaFuncSetAttribute(gemm_mega,  cudaFuncAttributeMaxDynamicSharedMemorySize, GSMEM);
    cudaFuncSetAttribute(gemm_oproj, cudaFuncAttributeMaxDynamicSharedMemorySize, GSMEM);

    const int Mq = B_ * NQ_;   // 131072

    // 1) conversions: big x; ctx + 4 weights in one launch
    f2h_kernel<<<4096, 256>>>(x, xh, Mq * QDIM_ / 4);
    f2h_multi<<<dim3(512, 5), 256>>>(
        ctx, ch,  B_ * NK_ * CDIM_ / 4,
        Wq,  wqh, INNER_ * QDIM_ / 4,
        Wk,  wkh, INNER_ * CDIM_ / 4,
        Wv,  wvh, INNER_ * CDIM_ / 4,
        Wo,  woh, QDIM_ * INNER_ / 4);

    // 2) all three input projections in one launch
    gemm_mega<<<3545, 128, GSMEM>>>(xh, ch, wqh, wkh, wvh, gq, gk, gv,
                                    qh, kh, vh);

    // 3) attention (fp16 in/out)
    attn_hmma<<<dim3(NQ_ / 256, HEADS_, B_), 256>>>(qh, kh, vh, oh);

    // 4) output projection (fp32 out, +bias, *gamma) via the fast GEMM
    gemm_oproj<<<3415, 128, GSMEM>>>(oh, woh, go, bo, out);
}